// round 1
// baseline (speedup 1.0000x reference)
#include <cuda_runtime.h>
#include <math.h>

// Shapes (fixed for this problem)
// B=4, T=256, C=2048, U=4, D=512, P=512, H=8, dk=64

__device__ float g_q[1024 * 512];
__device__ float g_k[8192 * 512];
__device__ float g_v[2048 * 512];
__device__ float g_att[1024 * 512];
__device__ float g_o[1024 * 512];

// ---------------------------------------------------------------------------
// LN (optional) + GEMM: out[16 rows x 512 cols] = LN(x) @ W + b
// Block: 256 threads, 16 rows per block. D = 512, NCOL = 512.
// ---------------------------------------------------------------------------
__global__ __launch_bounds__(256) void ln_gemm_kernel(
    const float* __restrict__ x,
    const float* __restrict__ lnw, const float* __restrict__ lnb,
    const float* __restrict__ w, const float* __restrict__ bias,
    float* __restrict__ out, int do_ln)
{
    __shared__ float xs[16][512];
    const int tid  = threadIdx.x;
    const int wid  = tid >> 5;
    const int lane = tid & 31;
    const int rowbase = blockIdx.x * 16;

    // Phase 1: LayerNorm 16 rows (2 rows per warp)
    for (int r = wid; r < 16; r += 8) {
        const float* xr = x + (size_t)(rowbase + r) * 512;
        if (do_ln) {
            float s = 0.f, ss = 0.f;
            #pragma unroll
            for (int j = lane; j < 512; j += 32) {
                float v = xr[j];
                s += v; ss += v * v;
            }
            #pragma unroll
            for (int o = 16; o; o >>= 1) {
                s  += __shfl_xor_sync(0xffffffffu, s, o);
                ss += __shfl_xor_sync(0xffffffffu, ss, o);
            }
            float mu   = s * (1.f / 512.f);
            float var  = ss * (1.f / 512.f) - mu * mu;
            float rstd = rsqrtf(var + 1e-5f);
            #pragma unroll
            for (int j = lane; j < 512; j += 32)
                xs[r][j] = (xr[j] - mu) * rstd * lnw[j] + lnb[j];
        } else {
            #pragma unroll
            for (int j = lane; j < 512; j += 32)
                xs[r][j] = xr[j];
        }
    }
    __syncthreads();

    // Phase 2: GEMM. Thread (row = tid/16, colgroup = tid%16) computes 8 cols
    // per column tile; 4 column tiles of 128 cover 512 cols.
    const int row = tid >> 4;
    const int cg  = tid & 15;
    for (int ct = 0; ct < 4; ++ct) {
        const int col0 = ct * 128 + cg * 8;
        float a0 = 0.f, a1 = 0.f, a2 = 0.f, a3 = 0.f;
        float a4 = 0.f, a5 = 0.f, a6 = 0.f, a7 = 0.f;
        #pragma unroll 4
        for (int d = 0; d < 512; ++d) {
            float xv = xs[row][d];
            const float4* wp = reinterpret_cast<const float4*>(w + (size_t)d * 512 + col0);
            float4 w0 = wp[0];
            float4 w1 = wp[1];
            a0 += xv * w0.x; a1 += xv * w0.y; a2 += xv * w0.z; a3 += xv * w0.w;
            a4 += xv * w1.x; a5 += xv * w1.y; a6 += xv * w1.z; a7 += xv * w1.w;
        }
        float* op = out + (size_t)(rowbase + row) * 512 + col0;
        op[0] = a0 + bias[col0 + 0];
        op[1] = a1 + bias[col0 + 1];
        op[2] = a2 + bias[col0 + 2];
        op[3] = a3 + bias[col0 + 3];
        op[4] = a4 + bias[col0 + 4];
        op[5] = a5 + bias[col0 + 5];
        op[6] = a6 + bias[col0 + 6];
        op[7] = a7 + bias[col0 + 7];
    }
}

// ---------------------------------------------------------------------------
// Fused ColBERT attention per (b, h, 16-token tile):
//   s[t][c] = max_u dot(q[t], k[c,u]) / 8 ;  softmax over c ;  out = attn @ V
// Online (flash-style) softmax over C=2048 in chunks of 32.
// Block: 256 threads (8 warps). Warp w owns token rows {w, w+8}; lane = cc.
// Grid: (B*T/16, H) = (64, 8).
// ---------------------------------------------------------------------------
__global__ __launch_bounds__(256) void attn_kernel(
    const float* __restrict__ q, const float* __restrict__ k,
    const float* __restrict__ v, float* __restrict__ outp)
{
    __shared__ float qs[16][64];
    __shared__ float ks[4 * 64 * 33];   // [u][d][cc], padded cc-dim to 33
    __shared__ float vs[32 * 64];       // [cc][d]

    const int tid  = threadIdx.x;
    const int w    = tid >> 5;
    const int lane = tid & 31;
    const int h    = blockIdx.y;
    const int bt0  = blockIdx.x * 16;

    // Load the 16x64 Q tile for this head
    for (int i = tid; i < 16 * 64; i += 256) {
        int r = i >> 6, d = i & 63;
        qs[r][d] = q[(size_t)(bt0 + r) * 512 + h * 64 + d];
    }

    float m0 = -1e30f, m1 = -1e30f;
    float l0 = 0.f,    l1 = 0.f;
    float o00 = 0.f, o01 = 0.f, o10 = 0.f, o11 = 0.f;

    for (int c0 = 0; c0 < 2048; c0 += 32) {
        __syncthreads();
        // Load K chunk: [32 cc][4 u][64 d] -> ks[u][d][cc]
        for (int i = tid; i < 32 * 4 * 64; i += 256) {
            int cc = i >> 8, rem = i & 255, u = rem >> 6, d = rem & 63;
            ks[(u * 64 + d) * 33 + cc] = k[(size_t)((c0 + cc) * 4 + u) * 512 + h * 64 + d];
        }
        // Load V chunk: [32 cc][64 d]
        for (int i = tid; i < 32 * 64; i += 256) {
            int cc = i >> 6, d = i & 63;
            vs[i] = v[(size_t)(c0 + cc) * 512 + h * 64 + d];
        }
        __syncthreads();

        // Scores: two token rows (w, w+8) x 4 u-slots, lane = context cc
        float a00 = 0.f, a01 = 0.f, a02 = 0.f, a03 = 0.f;
        float a10 = 0.f, a11 = 0.f, a12 = 0.f, a13 = 0.f;
        #pragma unroll 8
        for (int d = 0; d < 64; ++d) {
            float k0 = ks[(0 * 64 + d) * 33 + lane];
            float k1 = ks[(1 * 64 + d) * 33 + lane];
            float k2 = ks[(2 * 64 + d) * 33 + lane];
            float k3 = ks[(3 * 64 + d) * 33 + lane];
            float q0 = qs[w][d];
            float q1 = qs[w + 8][d];
            a00 += q0 * k0; a01 += q0 * k1; a02 += q0 * k2; a03 += q0 * k3;
            a10 += q1 * k0; a11 += q1 * k1; a12 += q1 * k2; a13 += q1 * k3;
        }
        float s0 = fmaxf(fmaxf(a00, a01), fmaxf(a02, a03)) * 0.125f;
        float s1 = fmaxf(fmaxf(a10, a11), fmaxf(a12, a13)) * 0.125f;

        // --- online softmax + AV, row tt = w ---
        {
            float cm = s0;
            #pragma unroll
            for (int o = 16; o; o >>= 1) cm = fmaxf(cm, __shfl_xor_sync(0xffffffffu, cm, o));
            float mn   = fmaxf(m0, cm);
            float corr = __expf(m0 - mn);
            float p    = __expf(s0 - mn);
            float ps   = p;
            #pragma unroll
            for (int o = 16; o; o >>= 1) ps += __shfl_xor_sync(0xffffffffu, ps, o);
            l0 = l0 * corr + ps;
            m0 = mn;
            o00 *= corr; o01 *= corr;
            #pragma unroll
            for (int cc = 0; cc < 32; ++cc) {
                float pc = __shfl_sync(0xffffffffu, p, cc);
                o00 += pc * vs[cc * 64 + lane];
                o01 += pc * vs[cc * 64 + lane + 32];
            }
        }
        // --- online softmax + AV, row tt = w + 8 ---
        {
            float cm = s1;
            #pragma unroll
            for (int o = 16; o; o >>= 1) cm = fmaxf(cm, __shfl_xor_sync(0xffffffffu, cm, o));
            float mn   = fmaxf(m1, cm);
            float corr = __expf(m1 - mn);
            float p    = __expf(s1 - mn);
            float ps   = p;
            #pragma unroll
            for (int o = 16; o; o >>= 1) ps += __shfl_xor_sync(0xffffffffu, ps, o);
            l1 = l1 * corr + ps;
            m1 = mn;
            o10 *= corr; o11 *= corr;
            #pragma unroll
            for (int cc = 0; cc < 32; ++cc) {
                float pc = __shfl_sync(0xffffffffu, p, cc);
                o10 += pc * vs[cc * 64 + lane];
                o11 += pc * vs[cc * 64 + lane + 32];
            }
        }
    }

    float inv0 = 1.f / l0;
    float inv1 = 1.f / l1;
    outp[(size_t)(bt0 + w)     * 512 + h * 64 + lane]      = o00 * inv0;
    outp[(size_t)(bt0 + w)     * 512 + h * 64 + lane + 32] = o01 * inv0;
    outp[(size_t)(bt0 + w + 8) * 512 + h * 64 + lane]      = o10 * inv1;
    outp[(size_t)(bt0 + w + 8) * 512 + h * 64 + lane + 32] = o11 * inv1;
}

// ---------------------------------------------------------------------------
extern "C" void kernel_launch(void* const* d_in, const int* in_sizes, int n_in,
                              void* d_out, int out_size)
{
    const float* model_embed = (const float*)d_in[0];   // [4,256,512]
    const float* ctx_key     = (const float*)d_in[1];   // [2048,4,512]
    const float* ctx_val     = (const float*)d_in[2];   // [2048,512]
    const float* ln1w = (const float*)d_in[3];
    const float* ln1b = (const float*)d_in[4];
    const float* ln2w = (const float*)d_in[5];
    const float* ln2b = (const float*)d_in[6];
    const float* ln3w = (const float*)d_in[7];
    const float* ln3b = (const float*)d_in[8];
    const float* ln4w = (const float*)d_in[9];
    const float* ln4b = (const float*)d_in[10];
    const float* wq = (const float*)d_in[11];
    const float* bq = (const float*)d_in[12];
    const float* wk = (const float*)d_in[13];
    const float* bk = (const float*)d_in[14];
    const float* wv = (const float*)d_in[15];
    const float* bv = (const float*)d_in[16];
    const float* wo = (const float*)d_in[17];
    const float* bo = (const float*)d_in[18];
    const float* wp = (const float*)d_in[19];
    const float* bp = (const float*)d_in[20];

    float *q, *k, *v, *att, *o;
    cudaGetSymbolAddress((void**)&q,   g_q);
    cudaGetSymbolAddress((void**)&k,   g_k);
    cudaGetSymbolAddress((void**)&v,   g_v);
    cudaGetSymbolAddress((void**)&att, g_att);
    cudaGetSymbolAddress((void**)&o,   g_o);

    // Q/K/V projections (with pre-LN)
    ln_gemm_kernel<<<64,  256>>>(model_embed, ln1w, ln1b, wq, bq, q, 1);   // 1024 rows
    ln_gemm_kernel<<<512, 256>>>(ctx_key,     ln2w, ln2b, wk, bk, k, 1);   // 8192 rows
    ln_gemm_kernel<<<128, 256>>>(ctx_val,     ln3w, ln3b, wv, bv, v, 1);   // 2048 rows

    // Fused MaxSim + softmax + AV
    attn_kernel<<<dim3(64, 8), 256>>>(q, k, v, att);

    // Output projection (no LN), then LN4 + final projection
    ln_gemm_kernel<<<64, 256>>>(att, nullptr, nullptr, wo, bo, o, 0);
    ln_gemm_kernel<<<64, 256>>>(o, ln4w, ln4b, wp, bp, (float*)d_out, 1);
}

// round 2
// speedup vs baseline: 1.7161x; 1.7161x over previous
#include <cuda_runtime.h>
#include <math.h>

// Shapes fixed: B=4, T=256, C=2048, U=4, D=512, P=512, H=8, dk=64

__device__ float g_xn [8192 * 512];
__device__ float g_q  [1024 * 512];
__device__ float g_k  [8192 * 512];
__device__ float g_v  [2048 * 512];
__device__ float g_att[1024 * 512];
__device__ float g_o  [1024 * 512];

// ---------------------------------------------------------------------------
// f32x2 packed helpers (FFMA2 path — PTX-only on sm_103a)
// ---------------------------------------------------------------------------
typedef unsigned long long u64;

__device__ __forceinline__ u64 pk2(float lo, float hi) {
    u64 r; asm("mov.b64 %0, {%1, %2};" : "=l"(r) : "f"(lo), "f"(hi)); return r;
}
__device__ __forceinline__ void upk2(u64 v, float& lo, float& hi) {
    asm("mov.b64 {%0, %1}, %2;" : "=f"(lo), "=f"(hi) : "l"(v));
}
__device__ __forceinline__ u64 fma2(u64 a, u64 b, u64 c) {
    u64 d; asm("fma.rn.f32x2 %0, %1, %2, %3;" : "=l"(d) : "l"(a), "l"(b), "l"(c)); return d;
}
__device__ __forceinline__ u64 mul2(u64 a, u64 b) {
    u64 d; asm("mul.rn.f32x2 %0, %1, %2;" : "=l"(d) : "l"(a), "l"(b)); return d;
}

// ---------------------------------------------------------------------------
// LayerNorm: one warp per row, D=512. grid = rows/8, block = 256.
// ---------------------------------------------------------------------------
__global__ __launch_bounds__(256) void ln_kernel(
    const float* __restrict__ x, const float* __restrict__ w,
    const float* __restrict__ b, float* __restrict__ out)
{
    const int lane = threadIdx.x & 31;
    const size_t row = (size_t)blockIdx.x * 8 + (threadIdx.x >> 5);
    const float* xr = x + row * 512;
    float4 xv[4];
    float s = 0.f, ss = 0.f;
    #pragma unroll
    for (int j = 0; j < 4; ++j) {
        xv[j] = *(const float4*)&xr[j * 128 + lane * 4];
        s  += xv[j].x + xv[j].y + xv[j].z + xv[j].w;
        ss += xv[j].x * xv[j].x + xv[j].y * xv[j].y + xv[j].z * xv[j].z + xv[j].w * xv[j].w;
    }
    #pragma unroll
    for (int o = 16; o; o >>= 1) {
        s  += __shfl_xor_sync(0xffffffffu, s, o);
        ss += __shfl_xor_sync(0xffffffffu, ss, o);
    }
    float mu = s * (1.f / 512.f);
    float rstd = rsqrtf(ss * (1.f / 512.f) - mu * mu + 1e-5f);
    float* orow = out + row * 512;
    #pragma unroll
    for (int j = 0; j < 4; ++j) {
        int col = j * 128 + lane * 4;
        float4 wv = *(const float4*)&w[col];
        float4 bv = *(const float4*)&b[col];
        float4 ov;
        ov.x = (xv[j].x - mu) * rstd * wv.x + bv.x;
        ov.y = (xv[j].y - mu) * rstd * wv.y + bv.y;
        ov.z = (xv[j].z - mu) * rstd * wv.z + bv.z;
        ov.w = (xv[j].w - mu) * rstd * wv.w + bv.w;
        *(float4*)&orow[col] = ov;
    }
}

// ---------------------------------------------------------------------------
// SGEMM: C[M x 512] = A[M x 512] @ B[512 x 512] + bias.
// Tile 64x128, BK=16, 256 threads, thread tile 4x8 (f32x2 paired along n).
// grid = (M/64, 4)
// ---------------------------------------------------------------------------
__global__ __launch_bounds__(256) void sgemm_kernel(
    const float* __restrict__ A, const float* __restrict__ B,
    const float* __restrict__ bias, float* __restrict__ C)
{
    __shared__ float As[16][68];    // k-major, padded
    __shared__ float Bs[16][132];

    const int tid = threadIdx.x;
    const int ty = tid >> 4;        // 0..15 (row group)
    const int tx = tid & 15;        // 0..15 (col group)
    const size_t m0 = (size_t)blockIdx.x * 64;
    const int n0 = blockIdx.y * 128;

    u64 acc[4][4];
    #pragma unroll
    for (int i = 0; i < 4; ++i)
        #pragma unroll
        for (int j = 0; j < 4; ++j) acc[i][j] = 0ull;

    const int ar = tid >> 2;            // 0..63
    const int ak = (tid & 3) * 4;       // 0,4,8,12
    const int bk = tid >> 4;            // 0..15
    const int bn = (tid & 15) * 8;

    for (int k0 = 0; k0 < 512; k0 += 16) {
        float4 a = *(const float4*)&A[(m0 + ar) * 512 + k0 + ak];
        As[ak + 0][ar] = a.x;
        As[ak + 1][ar] = a.y;
        As[ak + 2][ar] = a.z;
        As[ak + 3][ar] = a.w;
        const float4* bp = (const float4*)&B[(size_t)(k0 + bk) * 512 + n0 + bn];
        *(float4*)&Bs[bk][bn]     = bp[0];
        *(float4*)&Bs[bk][bn + 4] = bp[1];
        __syncthreads();

        #pragma unroll
        for (int kk = 0; kk < 16; ++kk) {
            float4 a4 = *(const float4*)&As[kk][ty * 4];
            const u64* bq = (const u64*)&Bs[kk][tx * 8];
            u64 b0 = bq[0], b1 = bq[1], b2 = bq[2], b3 = bq[3];
            u64 ax = pk2(a4.x, a4.x), ay = pk2(a4.y, a4.y);
            u64 az = pk2(a4.z, a4.z), aw = pk2(a4.w, a4.w);
            acc[0][0] = fma2(ax, b0, acc[0][0]); acc[0][1] = fma2(ax, b1, acc[0][1]);
            acc[0][2] = fma2(ax, b2, acc[0][2]); acc[0][3] = fma2(ax, b3, acc[0][3]);
            acc[1][0] = fma2(ay, b0, acc[1][0]); acc[1][1] = fma2(ay, b1, acc[1][1]);
            acc[1][2] = fma2(ay, b2, acc[1][2]); acc[1][3] = fma2(ay, b3, acc[1][3]);
            acc[2][0] = fma2(az, b0, acc[2][0]); acc[2][1] = fma2(az, b1, acc[2][1]);
            acc[2][2] = fma2(az, b2, acc[2][2]); acc[2][3] = fma2(az, b3, acc[2][3]);
            acc[3][0] = fma2(aw, b0, acc[3][0]); acc[3][1] = fma2(aw, b1, acc[3][1]);
            acc[3][2] = fma2(aw, b2, acc[3][2]); acc[3][3] = fma2(aw, b3, acc[3][3]);
        }
        __syncthreads();
    }

    const int col = n0 + tx * 8;
    float4 bb0 = *(const float4*)&bias[col];
    float4 bb1 = *(const float4*)&bias[col + 4];
    #pragma unroll
    for (int i = 0; i < 4; ++i) {
        float o0, o1, o2, o3, o4, o5, o6, o7;
        upk2(acc[i][0], o0, o1);
        upk2(acc[i][1], o2, o3);
        upk2(acc[i][2], o4, o5);
        upk2(acc[i][3], o6, o7);
        float* cp = C + (m0 + ty * 4 + i) * 512 + col;
        float4 r0 = make_float4(o0 + bb0.x, o1 + bb0.y, o2 + bb0.z, o3 + bb0.w);
        float4 r1 = make_float4(o4 + bb1.x, o5 + bb1.y, o6 + bb1.z, o7 + bb1.w);
        *(float4*)&cp[0] = r0;
        *(float4*)&cp[4] = r1;
    }
}

// ---------------------------------------------------------------------------
// Fused ColBERT attention. Block: 256 thr = 8 warps. grid (64, 8).
// Chunk of 64 contexts. Warps 0-3: rows 4w..4w+3, ccs 0-31 of chunk.
// Warps 4-7: same rows, ccs 32-63. Flash merge of the two halves at the end.
// Dynamic smem: qs[16*64] | ks[4][64cc][66d] | vs[64][64].
// ---------------------------------------------------------------------------
#define ATT_SMEM ((1024 + 4 * 64 * 66 + 4096) * 4)

__global__ __launch_bounds__(256) void attn_kernel(
    const float* __restrict__ q, const float* __restrict__ k,
    const float* __restrict__ v, float* __restrict__ outp)
{
    extern __shared__ float sm[];
    float* qs = sm;                 // [16][64]
    float* ks = sm + 1024;          // [u][cc][66]
    float* vs = ks + 4 * 64 * 66;   // [cc][64]

    const int tid  = threadIdx.x;
    const int w    = tid >> 5;
    const int lane = tid & 31;
    const int h    = blockIdx.y;
    const int bt0  = blockIdx.x * 16;
    const int r0   = (w & 3) * 4;
    const int cbase = (w >> 2) * 32;
    const int cc   = cbase + lane;

    for (int i = tid; i < 1024; i += 256)
        qs[i] = q[(size_t)(bt0 + (i >> 6)) * 512 + h * 64 + (i & 63)];

    float m[4] = {-1e30f, -1e30f, -1e30f, -1e30f};
    float l[4] = {0.f, 0.f, 0.f, 0.f};
    u64 o2[4]  = {0ull, 0ull, 0ull, 0ull};

    const float* kb0 = &ks[(0 * 64 + cc) * 66];
    const float* kb1 = &ks[(1 * 64 + cc) * 66];
    const float* kb2 = &ks[(2 * 64 + cc) * 66];
    const float* kb3 = &ks[(3 * 64 + cc) * 66];

    for (int c0 = 0; c0 < 2048; c0 += 64) {
        __syncthreads();
        #pragma unroll 4
        for (int i = tid; i < 16384; i += 256) {
            int d = i & 63, u = (i >> 6) & 3, ccl = i >> 8;
            ks[(u * 64 + ccl) * 66 + d] =
                k[((size_t)(c0 + ccl) * 4 + u) * 512 + h * 64 + d];
        }
        #pragma unroll 4
        for (int i = tid; i < 4096; i += 256)
            vs[i] = v[(size_t)(c0 + (i >> 6)) * 512 + h * 64 + (i & 63)];
        __syncthreads();

        // ---- scores: s[r][cc] = max_u sum_d q[r][d]*k[cc][u][d], f32x2 over d
        u64 acc[4][4];
        #pragma unroll
        for (int r = 0; r < 4; ++r)
            #pragma unroll
            for (int u = 0; u < 4; ++u) acc[r][u] = 0ull;

        #pragma unroll
        for (int d4 = 0; d4 < 64; d4 += 4) {
            float4 q0 = *(const float4*)&qs[(r0 + 0) * 64 + d4];
            float4 q1 = *(const float4*)&qs[(r0 + 1) * 64 + d4];
            float4 q2 = *(const float4*)&qs[(r0 + 2) * 64 + d4];
            float4 q3 = *(const float4*)&qs[(r0 + 3) * 64 + d4];
            u64 qp[4][2] = {
                {pk2(q0.x, q0.y), pk2(q0.z, q0.w)},
                {pk2(q1.x, q1.y), pk2(q1.z, q1.w)},
                {pk2(q2.x, q2.y), pk2(q2.z, q2.w)},
                {pk2(q3.x, q3.y), pk2(q3.z, q3.w)}};
            u64 k0a = *(const u64*)&kb0[d4], k0b = *(const u64*)&kb0[d4 + 2];
            u64 k1a = *(const u64*)&kb1[d4], k1b = *(const u64*)&kb1[d4 + 2];
            u64 k2a = *(const u64*)&kb2[d4], k2b = *(const u64*)&kb2[d4 + 2];
            u64 k3a = *(const u64*)&kb3[d4], k3b = *(const u64*)&kb3[d4 + 2];
            #pragma unroll
            for (int r = 0; r < 4; ++r) {
                acc[r][0] = fma2(qp[r][0], k0a, acc[r][0]);
                acc[r][0] = fma2(qp[r][1], k0b, acc[r][0]);
                acc[r][1] = fma2(qp[r][0], k1a, acc[r][1]);
                acc[r][1] = fma2(qp[r][1], k1b, acc[r][1]);
                acc[r][2] = fma2(qp[r][0], k2a, acc[r][2]);
                acc[r][2] = fma2(qp[r][1], k2b, acc[r][2]);
                acc[r][3] = fma2(qp[r][0], k3a, acc[r][3]);
                acc[r][3] = fma2(qp[r][1], k3b, acc[r][3]);
            }
        }

        float p[4];
        #pragma unroll
        for (int r = 0; r < 4; ++r) {
            float x0, x1, s;
            upk2(acc[r][0], x0, x1); s = x0 + x1;
            upk2(acc[r][1], x0, x1); s = fmaxf(s, x0 + x1);
            upk2(acc[r][2], x0, x1); s = fmaxf(s, x0 + x1);
            upk2(acc[r][3], x0, x1); s = fmaxf(s, x0 + x1);
            s *= 0.125f;
            float cm = s;
            #pragma unroll
            for (int o = 16; o; o >>= 1)
                cm = fmaxf(cm, __shfl_xor_sync(0xffffffffu, cm, o));
            float mn   = fmaxf(m[r], cm);
            float corr = __expf(m[r] - mn);
            p[r] = __expf(s - mn);
            float ps = p[r];
            #pragma unroll
            for (int o = 16; o; o >>= 1)
                ps += __shfl_xor_sync(0xffffffffu, ps, o);
            l[r] = l[r] * corr + ps;
            m[r] = mn;
            o2[r] = mul2(o2[r], pk2(corr, corr));
        }

        // ---- AV: o[r][2lane..2lane+1] += p[r][j] * v[j][2lane..]
        #pragma unroll 8
        for (int j = 0; j < 32; ++j) {
            u64 vj = *(const u64*)&vs[(cbase + j) * 64 + 2 * lane];
            float p0 = __shfl_sync(0xffffffffu, p[0], j);
            float p1 = __shfl_sync(0xffffffffu, p[1], j);
            float p2 = __shfl_sync(0xffffffffu, p[2], j);
            float p3 = __shfl_sync(0xffffffffu, p[3], j);
            o2[0] = fma2(pk2(p0, p0), vj, o2[0]);
            o2[1] = fma2(pk2(p1, p1), vj, o2[1]);
            o2[2] = fma2(pk2(p2, p2), vj, o2[2]);
            o2[3] = fma2(pk2(p3, p3), vj, o2[3]);
        }
    }

    // ---- merge the two cc-halves (flash combine), write output
    __syncthreads();
    float* obuf = sm;          // [16][64]
    float* mbuf = sm + 1024;   // [16]
    float* lbuf = sm + 1040;   // [16]
    if (w >= 4) {
        #pragma unroll
        for (int rr = 0; rr < 4; ++rr) {
            int r = r0 + rr;
            float lo, hi; upk2(o2[rr], lo, hi);
            obuf[r * 64 + 2 * lane]     = lo;
            obuf[r * 64 + 2 * lane + 1] = hi;
            if (lane == 0) { mbuf[r] = m[rr]; lbuf[r] = l[rr]; }
        }
    }
    __syncthreads();
    if (w < 4) {
        #pragma unroll
        for (int rr = 0; rr < 4; ++rr) {
            int r = r0 + rr;
            float mo = mbuf[r], lo_o = lbuf[r];
            float mn = fmaxf(m[rr], mo);
            float ca = __expf(m[rr] - mn);
            float cb = __expf(mo - mn);
            float inv = 1.f / (l[rr] * ca + lo_o * cb);
            float alo, ahi; upk2(o2[rr], alo, ahi);
            float blo = obuf[r * 64 + 2 * lane];
            float bhi = obuf[r * 64 + 2 * lane + 1];
            float* op = outp + (size_t)(bt0 + r) * 512 + h * 64 + 2 * lane;
            op[0] = (alo * ca + blo * cb) * inv;
            op[1] = (ahi * ca + bhi * cb) * inv;
        }
    }
}

// ---------------------------------------------------------------------------
extern "C" void kernel_launch(void* const* d_in, const int* in_sizes, int n_in,
                              void* d_out, int out_size)
{
    const float* model_embed = (const float*)d_in[0];
    const float* ctx_key     = (const float*)d_in[1];
    const float* ctx_val     = (const float*)d_in[2];
    const float* ln1w = (const float*)d_in[3];
    const float* ln1b = (const float*)d_in[4];
    const float* ln2w = (const float*)d_in[5];
    const float* ln2b = (const float*)d_in[6];
    const float* ln3w = (const float*)d_in[7];
    const float* ln3b = (const float*)d_in[8];
    const float* ln4w = (const float*)d_in[9];
    const float* ln4b = (const float*)d_in[10];
    const float* wq = (const float*)d_in[11];
    const float* bq = (const float*)d_in[12];
    const float* wk = (const float*)d_in[13];
    const float* bk = (const float*)d_in[14];
    const float* wv = (const float*)d_in[15];
    const float* bv = (const float*)d_in[16];
    const float* wo = (const float*)d_in[17];
    const float* bo = (const float*)d_in[18];
    const float* wp = (const float*)d_in[19];
    const float* bp = (const float*)d_in[20];

    float *xn, *q, *k, *v, *att, *o;
    cudaGetSymbolAddress((void**)&xn,  g_xn);
    cudaGetSymbolAddress((void**)&q,   g_q);
    cudaGetSymbolAddress((void**)&k,   g_k);
    cudaGetSymbolAddress((void**)&v,   g_v);
    cudaGetSymbolAddress((void**)&att, g_att);
    cudaGetSymbolAddress((void**)&o,   g_o);

    static int smem_set = 0;
    if (!smem_set) {
        cudaFuncSetAttribute(attn_kernel,
                             cudaFuncAttributeMaxDynamicSharedMemorySize, ATT_SMEM);
        smem_set = 1;
    }

    ln_kernel<<<128,  256>>>(model_embed, ln1w, ln1b, xn);
    sgemm_kernel<<<dim3(16, 4),  256>>>(xn, wq, bq, q);
    ln_kernel<<<1024, 256>>>(ctx_key, ln2w, ln2b, xn);
    sgemm_kernel<<<dim3(128, 4), 256>>>(xn, wk, bk, k);
    ln_kernel<<<256,  256>>>(ctx_val, ln3w, ln3b, xn);
    sgemm_kernel<<<dim3(32, 4),  256>>>(xn, wv, bv, v);

    attn_kernel<<<dim3(64, 8), 256, ATT_SMEM>>>(q, k, v, att);

    sgemm_kernel<<<dim3(16, 4), 256>>>(att, wo, bo, o);
    ln_kernel<<<128, 256>>>(o, ln4w, ln4b, xn);
    sgemm_kernel<<<dim3(16, 4), 256>>>(xn, wp, bp, (float*)d_out);
}

// round 3
// speedup vs baseline: 2.6284x; 1.5316x over previous
#include <cuda_runtime.h>
#include <math.h>

// Shapes fixed: B=4, T=256, C=2048, U=4, D=512, P=512, H=8, dk=64

__device__ float g_xn [8192 * 512];
__device__ float g_q  [1024 * 512];
__device__ float g_k  [8192 * 512];
__device__ float g_v  [2048 * 512];
__device__ float g_att[1024 * 512];
__device__ float g_o  [1024 * 512];

typedef unsigned long long u64;

__device__ __forceinline__ u64 pk2(float lo, float hi) {
    u64 r; asm("mov.b64 %0, {%1, %2};" : "=l"(r) : "f"(lo), "f"(hi)); return r;
}
__device__ __forceinline__ void upk2(u64 v, float& lo, float& hi) {
    asm("mov.b64 {%0, %1}, %2;" : "=f"(lo), "=f"(hi) : "l"(v));
}
__device__ __forceinline__ u64 fma2(u64 a, u64 b, u64 c) {
    u64 d; asm("fma.rn.f32x2 %0, %1, %2, %3;" : "=l"(d) : "l"(a), "l"(b), "l"(c)); return d;
}
__device__ __forceinline__ u64 mul2(u64 a, u64 b) {
    u64 d; asm("mul.rn.f32x2 %0, %1, %2;" : "=l"(d) : "l"(a), "l"(b)); return d;
}

// ---------------------------------------------------------------------------
// LayerNorm: one warp per row, D=512. grid = rows/8, block = 256.
// ---------------------------------------------------------------------------
__global__ __launch_bounds__(256) void ln_kernel(
    const float* __restrict__ x, const float* __restrict__ w,
    const float* __restrict__ b, float* __restrict__ out)
{
    const int lane = threadIdx.x & 31;
    const size_t row = (size_t)blockIdx.x * 8 + (threadIdx.x >> 5);
    const float* xr = x + row * 512;
    float4 xv[4];
    float s = 0.f, ss = 0.f;
    #pragma unroll
    for (int j = 0; j < 4; ++j) {
        xv[j] = *(const float4*)&xr[j * 128 + lane * 4];
        s  += xv[j].x + xv[j].y + xv[j].z + xv[j].w;
        ss += xv[j].x * xv[j].x + xv[j].y * xv[j].y + xv[j].z * xv[j].z + xv[j].w * xv[j].w;
    }
    #pragma unroll
    for (int o = 16; o; o >>= 1) {
        s  += __shfl_xor_sync(0xffffffffu, s, o);
        ss += __shfl_xor_sync(0xffffffffu, ss, o);
    }
    float mu = s * (1.f / 512.f);
    float rstd = rsqrtf(ss * (1.f / 512.f) - mu * mu + 1e-5f);
    float* orow = out + row * 512;
    #pragma unroll
    for (int j = 0; j < 4; ++j) {
        int col = j * 128 + lane * 4;
        float4 wv = *(const float4*)&w[col];
        float4 bv = *(const float4*)&b[col];
        float4 ov;
        ov.x = (xv[j].x - mu) * rstd * wv.x + bv.x;
        ov.y = (xv[j].y - mu) * rstd * wv.y + bv.y;
        ov.z = (xv[j].z - mu) * rstd * wv.z + bv.z;
        ov.w = (xv[j].w - mu) * rstd * wv.w + bv.w;
        *(float4*)&orow[col] = ov;
    }
}

// ---------------------------------------------------------------------------
// sgemm_big: 128x128 tile, BK=16, 256 threads, 8x8 thread tile (f32x2 on n).
// Double-buffered smem. grid = (M/128, 4).
// ---------------------------------------------------------------------------
__global__ __launch_bounds__(256) void sgemm_big(
    const float* __restrict__ A, const float* __restrict__ B,
    const float* __restrict__ bias, float* __restrict__ C)
{
    __shared__ float As[2][16][132];
    __shared__ float Bs[2][16][132];

    const int tid = threadIdx.x;
    const int ty = tid >> 4;            // 0..15, rows ty*8
    const int tx = tid & 15;            // 0..15, cols tx*8
    const size_t m0 = (size_t)blockIdx.x * 128;
    const int n0 = blockIdx.y * 128;

    const int ar  = tid >> 1;           // 0..127
    const int ak4 = (tid & 1) * 8;      // 0 or 8
    const int bk  = tid >> 4;           // 0..15
    const int bn  = (tid & 15) * 8;

    u64 acc[8][4];
    #pragma unroll
    for (int i = 0; i < 8; ++i)
        #pragma unroll
        for (int j = 0; j < 4; ++j) acc[i][j] = 0ull;

    // prologue: load tile 0
    float4 la0 = *(const float4*)&A[(m0 + ar) * 512 + ak4];
    float4 la1 = *(const float4*)&A[(m0 + ar) * 512 + ak4 + 4];
    float4 lb0 = *(const float4*)&B[(size_t)bk * 512 + n0 + bn];
    float4 lb1 = *(const float4*)&B[(size_t)bk * 512 + n0 + bn + 4];
    {
        As[0][ak4 + 0][ar] = la0.x; As[0][ak4 + 1][ar] = la0.y;
        As[0][ak4 + 2][ar] = la0.z; As[0][ak4 + 3][ar] = la0.w;
        As[0][ak4 + 4][ar] = la1.x; As[0][ak4 + 5][ar] = la1.y;
        As[0][ak4 + 6][ar] = la1.z; As[0][ak4 + 7][ar] = la1.w;
        *(float4*)&Bs[0][bk][bn]     = lb0;
        *(float4*)&Bs[0][bk][bn + 4] = lb1;
    }
    __syncthreads();

    for (int kt = 0; kt < 32; ++kt) {
        const int buf = kt & 1;
        if (kt < 31) {
            const int k0 = (kt + 1) * 16;
            la0 = *(const float4*)&A[(m0 + ar) * 512 + k0 + ak4];
            la1 = *(const float4*)&A[(m0 + ar) * 512 + k0 + ak4 + 4];
            lb0 = *(const float4*)&B[(size_t)(k0 + bk) * 512 + n0 + bn];
            lb1 = *(const float4*)&B[(size_t)(k0 + bk) * 512 + n0 + bn + 4];
        }
        #pragma unroll
        for (int kk = 0; kk < 16; ++kk) {
            float4 a0 = *(const float4*)&As[buf][kk][ty * 8];
            float4 a1 = *(const float4*)&As[buf][kk][ty * 8 + 4];
            const u64* bq = (const u64*)&Bs[buf][kk][tx * 8];
            u64 b0 = bq[0], b1 = bq[1], b2 = bq[2], b3 = bq[3];
            float av[8] = {a0.x, a0.y, a0.z, a0.w, a1.x, a1.y, a1.z, a1.w};
            #pragma unroll
            for (int i = 0; i < 8; ++i) {
                u64 ai = pk2(av[i], av[i]);
                acc[i][0] = fma2(ai, b0, acc[i][0]);
                acc[i][1] = fma2(ai, b1, acc[i][1]);
                acc[i][2] = fma2(ai, b2, acc[i][2]);
                acc[i][3] = fma2(ai, b3, acc[i][3]);
            }
        }
        if (kt < 31) {
            const int nb = 1 - buf;
            As[nb][ak4 + 0][ar] = la0.x; As[nb][ak4 + 1][ar] = la0.y;
            As[nb][ak4 + 2][ar] = la0.z; As[nb][ak4 + 3][ar] = la0.w;
            As[nb][ak4 + 4][ar] = la1.x; As[nb][ak4 + 5][ar] = la1.y;
            As[nb][ak4 + 6][ar] = la1.z; As[nb][ak4 + 7][ar] = la1.w;
            *(float4*)&Bs[nb][bk][bn]     = lb0;
            *(float4*)&Bs[nb][bk][bn + 4] = lb1;
        }
        __syncthreads();
    }

    const int col = n0 + tx * 8;
    float4 bb0 = *(const float4*)&bias[col];
    float4 bb1 = *(const float4*)&bias[col + 4];
    #pragma unroll
    for (int i = 0; i < 8; ++i) {
        float o0, o1, o2, o3, o4, o5, o6, o7;
        upk2(acc[i][0], o0, o1); upk2(acc[i][1], o2, o3);
        upk2(acc[i][2], o4, o5); upk2(acc[i][3], o6, o7);
        float* cp = C + (m0 + ty * 8 + i) * 512 + col;
        *(float4*)&cp[0] = make_float4(o0 + bb0.x, o1 + bb0.y, o2 + bb0.z, o3 + bb0.w);
        *(float4*)&cp[4] = make_float4(o4 + bb1.x, o5 + bb1.y, o6 + bb1.z, o7 + bb1.w);
    }
}

// ---------------------------------------------------------------------------
// sgemm_small: 32x128 tile, BK=16, 128 threads, 4x8 thread tile.
// Double-buffered. grid = (M/32, 4).
// ---------------------------------------------------------------------------
__global__ __launch_bounds__(128) void sgemm_small(
    const float* __restrict__ A, const float* __restrict__ B,
    const float* __restrict__ bias, float* __restrict__ C)
{
    __shared__ float As[2][16][36];
    __shared__ float Bs[2][16][132];

    const int tid = threadIdx.x;
    const int ty = tid >> 4;            // 0..7, rows ty*4
    const int tx = tid & 15;            // cols tx*8
    const size_t m0 = (size_t)blockIdx.x * 32;
    const int n0 = blockIdx.y * 128;

    const int ar  = tid >> 2;           // 0..31
    const int ak4 = (tid & 3) * 4;      // 0,4,8,12
    const int bk  = tid >> 4;           // 0..7 (rows bk, bk+8)
    const int bn  = (tid & 15) * 8;

    u64 acc[4][4];
    #pragma unroll
    for (int i = 0; i < 4; ++i)
        #pragma unroll
        for (int j = 0; j < 4; ++j) acc[i][j] = 0ull;

    float4 la = *(const float4*)&A[(m0 + ar) * 512 + ak4];
    float4 lb0 = *(const float4*)&B[(size_t)bk * 512 + n0 + bn];
    float4 lb1 = *(const float4*)&B[(size_t)bk * 512 + n0 + bn + 4];
    float4 lb2 = *(const float4*)&B[(size_t)(bk + 8) * 512 + n0 + bn];
    float4 lb3 = *(const float4*)&B[(size_t)(bk + 8) * 512 + n0 + bn + 4];
    {
        As[0][ak4 + 0][ar] = la.x; As[0][ak4 + 1][ar] = la.y;
        As[0][ak4 + 2][ar] = la.z; As[0][ak4 + 3][ar] = la.w;
        *(float4*)&Bs[0][bk][bn]         = lb0;
        *(float4*)&Bs[0][bk][bn + 4]     = lb1;
        *(float4*)&Bs[0][bk + 8][bn]     = lb2;
        *(float4*)&Bs[0][bk + 8][bn + 4] = lb3;
    }
    __syncthreads();

    for (int kt = 0; kt < 32; ++kt) {
        const int buf = kt & 1;
        if (kt < 31) {
            const int k0 = (kt + 1) * 16;
            la  = *(const float4*)&A[(m0 + ar) * 512 + k0 + ak4];
            lb0 = *(const float4*)&B[(size_t)(k0 + bk) * 512 + n0 + bn];
            lb1 = *(const float4*)&B[(size_t)(k0 + bk) * 512 + n0 + bn + 4];
            lb2 = *(const float4*)&B[(size_t)(k0 + bk + 8) * 512 + n0 + bn];
            lb3 = *(const float4*)&B[(size_t)(k0 + bk + 8) * 512 + n0 + bn + 4];
        }
        #pragma unroll
        for (int kk = 0; kk < 16; ++kk) {
            float4 a0 = *(const float4*)&As[buf][kk][ty * 4];
            const u64* bq = (const u64*)&Bs[buf][kk][tx * 8];
            u64 b0 = bq[0], b1 = bq[1], b2 = bq[2], b3 = bq[3];
            float av[4] = {a0.x, a0.y, a0.z, a0.w};
            #pragma unroll
            for (int i = 0; i < 4; ++i) {
                u64 ai = pk2(av[i], av[i]);
                acc[i][0] = fma2(ai, b0, acc[i][0]);
                acc[i][1] = fma2(ai, b1, acc[i][1]);
                acc[i][2] = fma2(ai, b2, acc[i][2]);
                acc[i][3] = fma2(ai, b3, acc[i][3]);
            }
        }
        if (kt < 31) {
            const int nb = 1 - buf;
            As[nb][ak4 + 0][ar] = la.x; As[nb][ak4 + 1][ar] = la.y;
            As[nb][ak4 + 2][ar] = la.z; As[nb][ak4 + 3][ar] = la.w;
            *(float4*)&Bs[nb][bk][bn]         = lb0;
            *(float4*)&Bs[nb][bk][bn + 4]     = lb1;
            *(float4*)&Bs[nb][bk + 8][bn]     = lb2;
            *(float4*)&Bs[nb][bk + 8][bn + 4] = lb3;
        }
        __syncthreads();
    }

    const int col = n0 + tx * 8;
    float4 bb0 = *(const float4*)&bias[col];
    float4 bb1 = *(const float4*)&bias[col + 4];
    #pragma unroll
    for (int i = 0; i < 4; ++i) {
        float o0, o1, o2, o3, o4, o5, o6, o7;
        upk2(acc[i][0], o0, o1); upk2(acc[i][1], o2, o3);
        upk2(acc[i][2], o4, o5); upk2(acc[i][3], o6, o7);
        float* cp = C + (m0 + ty * 4 + i) * 512 + col;
        *(float4*)&cp[0] = make_float4(o0 + bb0.x, o1 + bb0.y, o2 + bb0.z, o3 + bb0.w);
        *(float4*)&cp[4] = make_float4(o4 + bb1.x, o5 + bb1.y, o6 + bb1.z, o7 + bb1.w);
    }
}

// ---------------------------------------------------------------------------
// Fused ColBERT attention. Block 256 thr / 8 warps, grid (64, 8).
// Chunk = 64 contexts; warps 0-3 cover ccs 0-31, warps 4-7 ccs 32-63;
// each warp owns 4 token rows. Vectorized LDG.128 staging.
// ---------------------------------------------------------------------------
#define ATT_SMEM ((1024 + 4 * 64 * 66 + 4096) * 4)

__global__ __launch_bounds__(256) void attn_kernel(
    const float* __restrict__ q, const float* __restrict__ k,
    const float* __restrict__ v, float* __restrict__ outp)
{
    extern __shared__ float sm[];
    float* qs = sm;                 // [16][64]
    float* ks = sm + 1024;          // [u][cc][66]
    float* vs = ks + 4 * 64 * 66;   // [cc][64]

    const int tid  = threadIdx.x;
    const int w    = tid >> 5;
    const int lane = tid & 31;
    const int h    = blockIdx.y;
    const int bt0  = blockIdx.x * 16;
    const int r0   = (w & 3) * 4;
    const int cbase = (w >> 2) * 32;
    const int cc   = cbase + lane;

    for (int i = tid; i < 1024; i += 256)
        qs[i] = q[(size_t)(bt0 + (i >> 6)) * 512 + h * 64 + (i & 63)];

    float m[4] = {-1e30f, -1e30f, -1e30f, -1e30f};
    float l[4] = {0.f, 0.f, 0.f, 0.f};
    u64 o2[4]  = {0ull, 0ull, 0ull, 0ull};

    const float* kb0 = &ks[(0 * 64 + cc) * 66];
    const float* kb1 = &ks[(1 * 64 + cc) * 66];
    const float* kb2 = &ks[(2 * 64 + cc) * 66];
    const float* kb3 = &ks[(3 * 64 + cc) * 66];

    for (int c0 = 0; c0 < 2048; c0 += 64) {
        __syncthreads();
        // K chunk: 4096 float4s; per thread 16 LDG.128 + 32 STS.64
        #pragma unroll
        for (int j = 0; j < 16; ++j) {
            int i = tid + 256 * j;
            int dd = i & 15, u = (i >> 4) & 3, ccl = i >> 6;
            float4 t = *(const float4*)&k[((size_t)(c0 + ccl) * 4 + u) * 512 + h * 64 + dd * 4];
            float* dst = &ks[(u * 64 + ccl) * 66 + dd * 4];
            *(float2*)&dst[0] = make_float2(t.x, t.y);
            *(float2*)&dst[2] = make_float2(t.z, t.w);
        }
        // V chunk: 1024 float4s; per thread 4 LDG.128 + 4 STS.128
        #pragma unroll
        for (int j = 0; j < 4; ++j) {
            int i = tid + 256 * j;
            int dd = i & 15, ccl = i >> 4;
            *(float4*)&vs[ccl * 64 + dd * 4] =
                *(const float4*)&v[(size_t)(c0 + ccl) * 512 + h * 64 + dd * 4];
        }
        __syncthreads();

        // ---- scores
        u64 acc[4][4];
        #pragma unroll
        for (int r = 0; r < 4; ++r)
            #pragma unroll
            for (int u = 0; u < 4; ++u) acc[r][u] = 0ull;

        #pragma unroll
        for (int d4 = 0; d4 < 64; d4 += 4) {
            float4 q0 = *(const float4*)&qs[(r0 + 0) * 64 + d4];
            float4 q1 = *(const float4*)&qs[(r0 + 1) * 64 + d4];
            float4 q2 = *(const float4*)&qs[(r0 + 2) * 64 + d4];
            float4 q3 = *(const float4*)&qs[(r0 + 3) * 64 + d4];
            u64 qp[4][2] = {
                {pk2(q0.x, q0.y), pk2(q0.z, q0.w)},
                {pk2(q1.x, q1.y), pk2(q1.z, q1.w)},
                {pk2(q2.x, q2.y), pk2(q2.z, q2.w)},
                {pk2(q3.x, q3.y), pk2(q3.z, q3.w)}};
            u64 k0a = *(const u64*)&kb0[d4], k0b = *(const u64*)&kb0[d4 + 2];
            u64 k1a = *(const u64*)&kb1[d4], k1b = *(const u64*)&kb1[d4 + 2];
            u64 k2a = *(const u64*)&kb2[d4], k2b = *(const u64*)&kb2[d4 + 2];
            u64 k3a = *(const u64*)&kb3[d4], k3b = *(const u64*)&kb3[d4 + 2];
            #pragma unroll
            for (int r = 0; r < 4; ++r) {
                acc[r][0] = fma2(qp[r][0], k0a, acc[r][0]);
                acc[r][0] = fma2(qp[r][1], k0b, acc[r][0]);
                acc[r][1] = fma2(qp[r][0], k1a, acc[r][1]);
                acc[r][1] = fma2(qp[r][1], k1b, acc[r][1]);
                acc[r][2] = fma2(qp[r][0], k2a, acc[r][2]);
                acc[r][2] = fma2(qp[r][1], k2b, acc[r][2]);
                acc[r][3] = fma2(qp[r][0], k3a, acc[r][3]);
                acc[r][3] = fma2(qp[r][1], k3b, acc[r][3]);
            }
        }

        float p[4];
        #pragma unroll
        for (int r = 0; r < 4; ++r) {
            float x0, x1, s;
            upk2(acc[r][0], x0, x1); s = x0 + x1;
            upk2(acc[r][1], x0, x1); s = fmaxf(s, x0 + x1);
            upk2(acc[r][2], x0, x1); s = fmaxf(s, x0 + x1);
            upk2(acc[r][3], x0, x1); s = fmaxf(s, x0 + x1);
            s *= 0.125f;
            float cm = s;
            #pragma unroll
            for (int o = 16; o; o >>= 1)
                cm = fmaxf(cm, __shfl_xor_sync(0xffffffffu, cm, o));
            float mn   = fmaxf(m[r], cm);
            float corr = __expf(m[r] - mn);
            p[r] = __expf(s - mn);
            float ps = p[r];
            #pragma unroll
            for (int o = 16; o; o >>= 1)
                ps += __shfl_xor_sync(0xffffffffu, ps, o);
            l[r] = l[r] * corr + ps;
            m[r] = mn;
            o2[r] = mul2(o2[r], pk2(corr, corr));
        }

        // ---- AV
        #pragma unroll 8
        for (int j = 0; j < 32; ++j) {
            u64 vj = *(const u64*)&vs[(cbase + j) * 64 + 2 * lane];
            float p0 = __shfl_sync(0xffffffffu, p[0], j);
            float p1 = __shfl_sync(0xffffffffu, p[1], j);
            float p2 = __shfl_sync(0xffffffffu, p[2], j);
            float p3 = __shfl_sync(0xffffffffu, p[3], j);
            o2[0] = fma2(pk2(p0, p0), vj, o2[0]);
            o2[1] = fma2(pk2(p1, p1), vj, o2[1]);
            o2[2] = fma2(pk2(p2, p2), vj, o2[2]);
            o2[3] = fma2(pk2(p3, p3), vj, o2[3]);
        }
    }

    // ---- merge the two cc-halves, write output
    __syncthreads();
    float* obuf = sm;          // [16][64]
    float* mbuf = sm + 1024;   // [16]
    float* lbuf = sm + 1040;   // [16]
    if (w >= 4) {
        #pragma unroll
        for (int rr = 0; rr < 4; ++rr) {
            int r = r0 + rr;
            float lo, hi; upk2(o2[rr], lo, hi);
            obuf[r * 64 + 2 * lane]     = lo;
            obuf[r * 64 + 2 * lane + 1] = hi;
            if (lane == 0) { mbuf[r] = m[rr]; lbuf[r] = l[rr]; }
        }
    }
    __syncthreads();
    if (w < 4) {
        #pragma unroll
        for (int rr = 0; rr < 4; ++rr) {
            int r = r0 + rr;
            float mo = mbuf[r], lo_o = lbuf[r];
            float mn = fmaxf(m[rr], mo);
            float ca = __expf(m[rr] - mn);
            float cb = __expf(mo - mn);
            float inv = 1.f / (l[rr] * ca + lo_o * cb);
            float alo, ahi; upk2(o2[rr], alo, ahi);
            float blo = obuf[r * 64 + 2 * lane];
            float bhi = obuf[r * 64 + 2 * lane + 1];
            float* op = outp + (size_t)(bt0 + r) * 512 + h * 64 + 2 * lane;
            op[0] = (alo * ca + blo * cb) * inv;
            op[1] = (ahi * ca + bhi * cb) * inv;
        }
    }
}

// ---------------------------------------------------------------------------
extern "C" void kernel_launch(void* const* d_in, const int* in_sizes, int n_in,
                              void* d_out, int out_size)
{
    const float* model_embed = (const float*)d_in[0];
    const float* ctx_key     = (const float*)d_in[1];
    const float* ctx_val     = (const float*)d_in[2];
    const float* ln1w = (const float*)d_in[3];
    const float* ln1b = (const float*)d_in[4];
    const float* ln2w = (const float*)d_in[5];
    const float* ln2b = (const float*)d_in[6];
    const float* ln3w = (const float*)d_in[7];
    const float* ln3b = (const float*)d_in[8];
    const float* ln4w = (const float*)d_in[9];
    const float* ln4b = (const float*)d_in[10];
    const float* wq = (const float*)d_in[11];
    const float* bq = (const float*)d_in[12];
    const float* wk = (const float*)d_in[13];
    const float* bk = (const float*)d_in[14];
    const float* wv = (const float*)d_in[15];
    const float* bv = (const float*)d_in[16];
    const float* wo = (const float*)d_in[17];
    const float* bo = (const float*)d_in[18];
    const float* wp = (const float*)d_in[19];
    const float* bp = (const float*)d_in[20];

    float *xn, *q, *k, *v, *att, *o;
    cudaGetSymbolAddress((void**)&xn,  g_xn);
    cudaGetSymbolAddress((void**)&q,   g_q);
    cudaGetSymbolAddress((void**)&k,   g_k);
    cudaGetSymbolAddress((void**)&v,   g_v);
    cudaGetSymbolAddress((void**)&att, g_att);
    cudaGetSymbolAddress((void**)&o,   g_o);

    static int smem_set = 0;
    if (!smem_set) {
        cudaFuncSetAttribute(attn_kernel,
                             cudaFuncAttributeMaxDynamicSharedMemorySize, ATT_SMEM);
        smem_set = 1;
    }

    ln_kernel<<<128,  256>>>(model_embed, ln1w, ln1b, xn);
    sgemm_small<<<dim3(32, 4), 128>>>(xn, wq, bq, q);
    ln_kernel<<<1024, 256>>>(ctx_key, ln2w, ln2b, xn);
    sgemm_big<<<dim3(64, 4), 256>>>(xn, wk, bk, k);
    ln_kernel<<<256,  256>>>(ctx_val, ln3w, ln3b, xn);
    sgemm_small<<<dim3(64, 4), 128>>>(xn, wv, bv, v);

    attn_kernel<<<dim3(64, 8), 256, ATT_SMEM>>>(q, k, v, att);

    sgemm_small<<<dim3(32, 4), 128>>>(att, wo, bo, o);
    ln_kernel<<<128, 256>>>(o, ln4w, ln4b, xn);
    sgemm_small<<<dim3(32, 4), 128>>>(xn, wp, bp, (float*)d_out);
}

// round 4
// speedup vs baseline: 2.9588x; 1.1257x over previous
#include <cuda_runtime.h>
#include <math.h>

// Shapes fixed: B=4, T=256, C=2048, U=4, D=512, P=512, H=8, dk=64

__device__ float g_xn [8192 * 512];
__device__ float g_q  [1024 * 512];
__device__ float g_k  [8192 * 512];
__device__ float g_v  [2048 * 512];
__device__ float g_att[1024 * 512];
__device__ float g_o  [1024 * 512];

typedef unsigned long long u64;

__device__ __forceinline__ u64 pk2(float lo, float hi) {
    u64 r; asm("mov.b64 %0, {%1, %2};" : "=l"(r) : "f"(lo), "f"(hi)); return r;
}
__device__ __forceinline__ void upk2(u64 v, float& lo, float& hi) {
    asm("mov.b64 {%0, %1}, %2;" : "=f"(lo), "=f"(hi) : "l"(v));
}
__device__ __forceinline__ u64 fma2(u64 a, u64 b, u64 c) {
    u64 d; asm("fma.rn.f32x2 %0, %1, %2, %3;" : "=l"(d) : "l"(a), "l"(b), "l"(c)); return d;
}
__device__ __forceinline__ u64 mul2(u64 a, u64 b) {
    u64 d; asm("mul.rn.f32x2 %0, %1, %2;" : "=l"(d) : "l"(a), "l"(b)); return d;
}

// ---------------------------------------------------------------------------
// LayerNorm: one warp per row, D=512. grid = rows/8, block = 256.
// ---------------------------------------------------------------------------
__global__ __launch_bounds__(256) void ln_kernel(
    const float* __restrict__ x, const float* __restrict__ w,
    const float* __restrict__ b, float* __restrict__ out)
{
    const int lane = threadIdx.x & 31;
    const size_t row = (size_t)blockIdx.x * 8 + (threadIdx.x >> 5);
    const float* xr = x + row * 512;
    float4 xv[4];
    float s = 0.f, ss = 0.f;
    #pragma unroll
    for (int j = 0; j < 4; ++j) {
        xv[j] = *(const float4*)&xr[j * 128 + lane * 4];
        s  += xv[j].x + xv[j].y + xv[j].z + xv[j].w;
        ss += xv[j].x * xv[j].x + xv[j].y * xv[j].y + xv[j].z * xv[j].z + xv[j].w * xv[j].w;
    }
    #pragma unroll
    for (int o = 16; o; o >>= 1) {
        s  += __shfl_xor_sync(0xffffffffu, s, o);
        ss += __shfl_xor_sync(0xffffffffu, ss, o);
    }
    float mu = s * (1.f / 512.f);
    float rstd = rsqrtf(ss * (1.f / 512.f) - mu * mu + 1e-5f);
    float* orow = out + row * 512;
    #pragma unroll
    for (int j = 0; j < 4; ++j) {
        int col = j * 128 + lane * 4;
        float4 wv = *(const float4*)&w[col];
        float4 bv = *(const float4*)&b[col];
        float4 ov;
        ov.x = (xv[j].x - mu) * rstd * wv.x + bv.x;
        ov.y = (xv[j].y - mu) * rstd * wv.y + bv.y;
        ov.z = (xv[j].z - mu) * rstd * wv.z + bv.z;
        ov.w = (xv[j].w - mu) * rstd * wv.w + bv.w;
        *(float4*)&orow[col] = ov;
    }
}

// ---------------------------------------------------------------------------
// sgemm_big: 128x128 tile, BK=16, 256 threads, 8x8 thread tile.
// Column mapping: thread owns pairs {2tx+32j, 2tx+32j+1}, j=0..3 ->
// conflict-free LDS.64 B-fragment reads. Double-buffered. grid (M/128, 4).
// ---------------------------------------------------------------------------
__global__ __launch_bounds__(256) void sgemm_big(
    const float* __restrict__ A, const float* __restrict__ B,
    const float* __restrict__ bias, float* __restrict__ C)
{
    __shared__ float As[2][16][132];
    __shared__ float Bs[2][16][132];

    const int tid = threadIdx.x;
    const int ty = tid >> 4;
    const int tx = tid & 15;
    const size_t m0 = (size_t)blockIdx.x * 128;
    const int n0 = blockIdx.y * 128;

    const int ar  = tid >> 1;
    const int ak4 = (tid & 1) * 8;
    const int bk  = tid >> 4;
    const int bn  = (tid & 15) * 8;

    u64 acc[8][4];
    #pragma unroll
    for (int i = 0; i < 8; ++i)
        #pragma unroll
        for (int j = 0; j < 4; ++j) acc[i][j] = 0ull;

    float4 la0 = *(const float4*)&A[(m0 + ar) * 512 + ak4];
    float4 la1 = *(const float4*)&A[(m0 + ar) * 512 + ak4 + 4];
    float4 lb0 = *(const float4*)&B[(size_t)bk * 512 + n0 + bn];
    float4 lb1 = *(const float4*)&B[(size_t)bk * 512 + n0 + bn + 4];
    {
        As[0][ak4 + 0][ar] = la0.x; As[0][ak4 + 1][ar] = la0.y;
        As[0][ak4 + 2][ar] = la0.z; As[0][ak4 + 3][ar] = la0.w;
        As[0][ak4 + 4][ar] = la1.x; As[0][ak4 + 5][ar] = la1.y;
        As[0][ak4 + 6][ar] = la1.z; As[0][ak4 + 7][ar] = la1.w;
        *(float4*)&Bs[0][bk][bn]     = lb0;
        *(float4*)&Bs[0][bk][bn + 4] = lb1;
    }
    __syncthreads();

    for (int kt = 0; kt < 32; ++kt) {
        const int buf = kt & 1;
        if (kt < 31) {
            const int k0 = (kt + 1) * 16;
            la0 = *(const float4*)&A[(m0 + ar) * 512 + k0 + ak4];
            la1 = *(const float4*)&A[(m0 + ar) * 512 + k0 + ak4 + 4];
            lb0 = *(const float4*)&B[(size_t)(k0 + bk) * 512 + n0 + bn];
            lb1 = *(const float4*)&B[(size_t)(k0 + bk) * 512 + n0 + bn + 4];
        }
        #pragma unroll
        for (int kk = 0; kk < 16; ++kk) {
            float4 a0 = *(const float4*)&As[buf][kk][ty * 8];
            float4 a1 = *(const float4*)&As[buf][kk][ty * 8 + 4];
            u64 b0 = *(const u64*)&Bs[buf][kk][2 * tx];
            u64 b1 = *(const u64*)&Bs[buf][kk][2 * tx + 32];
            u64 b2 = *(const u64*)&Bs[buf][kk][2 * tx + 64];
            u64 b3 = *(const u64*)&Bs[buf][kk][2 * tx + 96];
            float av[8] = {a0.x, a0.y, a0.z, a0.w, a1.x, a1.y, a1.z, a1.w};
            #pragma unroll
            for (int i = 0; i < 8; ++i) {
                u64 ai = pk2(av[i], av[i]);
                acc[i][0] = fma2(ai, b0, acc[i][0]);
                acc[i][1] = fma2(ai, b1, acc[i][1]);
                acc[i][2] = fma2(ai, b2, acc[i][2]);
                acc[i][3] = fma2(ai, b3, acc[i][3]);
            }
        }
        if (kt < 31) {
            const int nb = 1 - buf;
            As[nb][ak4 + 0][ar] = la0.x; As[nb][ak4 + 1][ar] = la0.y;
            As[nb][ak4 + 2][ar] = la0.z; As[nb][ak4 + 3][ar] = la0.w;
            As[nb][ak4 + 4][ar] = la1.x; As[nb][ak4 + 5][ar] = la1.y;
            As[nb][ak4 + 6][ar] = la1.z; As[nb][ak4 + 7][ar] = la1.w;
            *(float4*)&Bs[nb][bk][bn]     = lb0;
            *(float4*)&Bs[nb][bk][bn + 4] = lb1;
        }
        __syncthreads();
    }

    #pragma unroll
    for (int j = 0; j < 4; ++j) {
        const int col = n0 + 2 * tx + 32 * j;
        float2 bb = *(const float2*)&bias[col];
        #pragma unroll
        for (int i = 0; i < 8; ++i) {
            float o0, o1; upk2(acc[i][j], o0, o1);
            *(float2*)&C[(m0 + ty * 8 + i) * 512 + col] =
                make_float2(o0 + bb.x, o1 + bb.y);
        }
    }
}

// ---------------------------------------------------------------------------
// sgemm_small: 32x128 tile, BK=16, 128 threads, 4x8 thread tile,
// same pair-strided column mapping. grid (M/32, 4).
// ---------------------------------------------------------------------------
__global__ __launch_bounds__(128) void sgemm_small(
    const float* __restrict__ A, const float* __restrict__ B,
    const float* __restrict__ bias, float* __restrict__ C)
{
    __shared__ float As[2][16][36];
    __shared__ float Bs[2][16][132];

    const int tid = threadIdx.x;
    const int ty = tid >> 4;
    const int tx = tid & 15;
    const size_t m0 = (size_t)blockIdx.x * 32;
    const int n0 = blockIdx.y * 128;

    const int ar  = tid >> 2;
    const int ak4 = (tid & 3) * 4;
    const int bk  = tid >> 4;
    const int bn  = (tid & 15) * 8;

    u64 acc[4][4];
    #pragma unroll
    for (int i = 0; i < 4; ++i)
        #pragma unroll
        for (int j = 0; j < 4; ++j) acc[i][j] = 0ull;

    float4 la = *(const float4*)&A[(m0 + ar) * 512 + ak4];
    float4 lb0 = *(const float4*)&B[(size_t)bk * 512 + n0 + bn];
    float4 lb1 = *(const float4*)&B[(size_t)bk * 512 + n0 + bn + 4];
    float4 lb2 = *(const float4*)&B[(size_t)(bk + 8) * 512 + n0 + bn];
    float4 lb3 = *(const float4*)&B[(size_t)(bk + 8) * 512 + n0 + bn + 4];
    {
        As[0][ak4 + 0][ar] = la.x; As[0][ak4 + 1][ar] = la.y;
        As[0][ak4 + 2][ar] = la.z; As[0][ak4 + 3][ar] = la.w;
        *(float4*)&Bs[0][bk][bn]         = lb0;
        *(float4*)&Bs[0][bk][bn + 4]     = lb1;
        *(float4*)&Bs[0][bk + 8][bn]     = lb2;
        *(float4*)&Bs[0][bk + 8][bn + 4] = lb3;
    }
    __syncthreads();

    for (int kt = 0; kt < 32; ++kt) {
        const int buf = kt & 1;
        if (kt < 31) {
            const int k0 = (kt + 1) * 16;
            la  = *(const float4*)&A[(m0 + ar) * 512 + k0 + ak4];
            lb0 = *(const float4*)&B[(size_t)(k0 + bk) * 512 + n0 + bn];
            lb1 = *(const float4*)&B[(size_t)(k0 + bk) * 512 + n0 + bn + 4];
            lb2 = *(const float4*)&B[(size_t)(k0 + bk + 8) * 512 + n0 + bn];
            lb3 = *(const float4*)&B[(size_t)(k0 + bk + 8) * 512 + n0 + bn + 4];
        }
        #pragma unroll
        for (int kk = 0; kk < 16; ++kk) {
            float4 a0 = *(const float4*)&As[buf][kk][ty * 4];
            u64 b0 = *(const u64*)&Bs[buf][kk][2 * tx];
            u64 b1 = *(const u64*)&Bs[buf][kk][2 * tx + 32];
            u64 b2 = *(const u64*)&Bs[buf][kk][2 * tx + 64];
            u64 b3 = *(const u64*)&Bs[buf][kk][2 * tx + 96];
            float av[4] = {a0.x, a0.y, a0.z, a0.w};
            #pragma unroll
            for (int i = 0; i < 4; ++i) {
                u64 ai = pk2(av[i], av[i]);
                acc[i][0] = fma2(ai, b0, acc[i][0]);
                acc[i][1] = fma2(ai, b1, acc[i][1]);
                acc[i][2] = fma2(ai, b2, acc[i][2]);
                acc[i][3] = fma2(ai, b3, acc[i][3]);
            }
        }
        if (kt < 31) {
            const int nb = 1 - buf;
            As[nb][ak4 + 0][ar] = la.x; As[nb][ak4 + 1][ar] = la.y;
            As[nb][ak4 + 2][ar] = la.z; As[nb][ak4 + 3][ar] = la.w;
            *(float4*)&Bs[nb][bk][bn]         = lb0;
            *(float4*)&Bs[nb][bk][bn + 4]     = lb1;
            *(float4*)&Bs[nb][bk + 8][bn]     = lb2;
            *(float4*)&Bs[nb][bk + 8][bn + 4] = lb3;
        }
        __syncthreads();
    }

    #pragma unroll
    for (int j = 0; j < 4; ++j) {
        const int col = n0 + 2 * tx + 32 * j;
        float2 bb = *(const float2*)&bias[col];
        #pragma unroll
        for (int i = 0; i < 4; ++i) {
            float o0, o1; upk2(acc[i][j], o0, o1);
            *(float2*)&C[(m0 + ty * 4 + i) * 512 + col] =
                make_float2(o0 + bb.x, o1 + bb.y);
        }
    }
}

// ---------------------------------------------------------------------------
// Fused ColBERT attention. Block 256 thr / 8 warps, grid (64, 8).
// Chunk = 64 contexts; warps 0-3: ccs 0-31, warps 4-7: ccs 32-63; 4 rows/warp.
// K smem layout [u][cc][64] with XOR swizzle (d ^ 4*(cc&7)): conflict-free
// LDS.128 K reads AND aligned STS.128 staging, q stays broadcast.
// AV uses smem-transposed p (no shfl broadcast).
// smem: qs[1024] | ks[16384] | vs[4096] | ps[8*32*4]
// ---------------------------------------------------------------------------
#define ATT_SMEM ((1024 + 16384 + 4096 + 1024) * 4)

__global__ __launch_bounds__(256) void attn_kernel(
    const float* __restrict__ q, const float* __restrict__ k,
    const float* __restrict__ v, float* __restrict__ outp)
{
    extern __shared__ float sm[];
    float* qs = sm;                  // [16][64]
    float* ks = sm + 1024;           // [u][cc][64] swizzled
    float* vs = ks + 16384;          // [cc][64]
    float* ps = vs + 4096;           // [warp][cc][4]

    const int tid  = threadIdx.x;
    const int w    = tid >> 5;
    const int lane = tid & 31;
    const int h    = blockIdx.y;
    const int bt0  = blockIdx.x * 16;
    const int r0   = (w & 3) * 4;
    const int cbase = (w >> 2) * 32;
    const int cc   = cbase + lane;
    const int sw   = (lane & 7) << 2;

    for (int i = tid; i < 1024; i += 256)
        qs[i] = q[(size_t)(bt0 + (i >> 6)) * 512 + h * 64 + (i & 63)];

    float m[4] = {-1e30f, -1e30f, -1e30f, -1e30f};
    float l[4] = {0.f, 0.f, 0.f, 0.f};
    u64 o2[4]  = {0ull, 0ull, 0ull, 0ull};

    const float* kb0 = ks + cc * 64;
    const float* kb1 = kb0 + 4096;
    const float* kb2 = kb0 + 8192;
    const float* kb3 = kb0 + 12288;
    float* pw = ps + w * 128;

    for (int c0 = 0; c0 < 2048; c0 += 64) {
        __syncthreads();
        // K chunk: 4096 float4s, swizzled STS.128 (conflict-free)
        #pragma unroll
        for (int j = 0; j < 16; ++j) {
            int i = tid + 256 * j;
            int dd = i & 15, u = (i >> 4) & 3, ccl = i >> 6;
            float4 t = *(const float4*)&k[((size_t)(c0 + ccl) * 4 + u) * 512 + h * 64 + dd * 4];
            *(float4*)&ks[u * 4096 + ccl * 64 + ((dd << 2) ^ ((ccl & 7) << 2))] = t;
        }
        // V chunk: plain [cc][64]
        #pragma unroll
        for (int j = 0; j < 4; ++j) {
            int i = tid + 256 * j;
            int dd = i & 15, ccl = i >> 4;
            *(float4*)&vs[ccl * 64 + dd * 4] =
                *(const float4*)&v[(size_t)(c0 + ccl) * 512 + h * 64 + dd * 4];
        }
        __syncthreads();

        // ---- scores
        u64 acc[4][4];
        #pragma unroll
        for (int r = 0; r < 4; ++r)
            #pragma unroll
            for (int u = 0; u < 4; ++u) acc[r][u] = 0ull;

        #pragma unroll
        for (int d4 = 0; d4 < 64; d4 += 4) {
            const int off = d4 ^ sw;
            float4 k0 = *(const float4*)&kb0[off];
            float4 k1 = *(const float4*)&kb1[off];
            float4 k2 = *(const float4*)&kb2[off];
            float4 k3 = *(const float4*)&kb3[off];
            u64 k0a = pk2(k0.x, k0.y), k0b = pk2(k0.z, k0.w);
            u64 k1a = pk2(k1.x, k1.y), k1b = pk2(k1.z, k1.w);
            u64 k2a = pk2(k2.x, k2.y), k2b = pk2(k2.z, k2.w);
            u64 k3a = pk2(k3.x, k3.y), k3b = pk2(k3.z, k3.w);
            float4 q0 = *(const float4*)&qs[(r0 + 0) * 64 + d4];
            float4 q1 = *(const float4*)&qs[(r0 + 1) * 64 + d4];
            float4 q2 = *(const float4*)&qs[(r0 + 2) * 64 + d4];
            float4 q3 = *(const float4*)&qs[(r0 + 3) * 64 + d4];
            u64 qp[4][2] = {
                {pk2(q0.x, q0.y), pk2(q0.z, q0.w)},
                {pk2(q1.x, q1.y), pk2(q1.z, q1.w)},
                {pk2(q2.x, q2.y), pk2(q2.z, q2.w)},
                {pk2(q3.x, q3.y), pk2(q3.z, q3.w)}};
            #pragma unroll
            for (int r = 0; r < 4; ++r) {
                acc[r][0] = fma2(qp[r][0], k0a, acc[r][0]);
                acc[r][0] = fma2(qp[r][1], k0b, acc[r][0]);
                acc[r][1] = fma2(qp[r][0], k1a, acc[r][1]);
                acc[r][1] = fma2(qp[r][1], k1b, acc[r][1]);
                acc[r][2] = fma2(qp[r][0], k2a, acc[r][2]);
                acc[r][2] = fma2(qp[r][1], k2b, acc[r][2]);
                acc[r][3] = fma2(qp[r][0], k3a, acc[r][3]);
                acc[r][3] = fma2(qp[r][1], k3b, acc[r][3]);
            }
        }

        float pv[4];
        #pragma unroll
        for (int r = 0; r < 4; ++r) {
            float x0, x1, s;
            upk2(acc[r][0], x0, x1); s = x0 + x1;
            upk2(acc[r][1], x0, x1); s = fmaxf(s, x0 + x1);
            upk2(acc[r][2], x0, x1); s = fmaxf(s, x0 + x1);
            upk2(acc[r][3], x0, x1); s = fmaxf(s, x0 + x1);
            s *= 0.125f;
            float cm = s;
            #pragma unroll
            for (int o = 16; o; o >>= 1)
                cm = fmaxf(cm, __shfl_xor_sync(0xffffffffu, cm, o));
            float mn   = fmaxf(m[r], cm);
            float corr = __expf(m[r] - mn);
            pv[r] = __expf(s - mn);
            float pssum = pv[r];
            #pragma unroll
            for (int o = 16; o; o >>= 1)
                pssum += __shfl_xor_sync(0xffffffffu, pssum, o);
            l[r] = l[r] * corr + pssum;
            m[r] = mn;
            o2[r] = mul2(o2[r], pk2(corr, corr));
        }

        // transpose p through smem: ps[w][lane][r]
        *(float4*)&pw[lane * 4] = make_float4(pv[0], pv[1], pv[2], pv[3]);
        __syncwarp();

        // ---- AV: o[r][2lane..] += p[r][j] * v[j][2lane..]
        #pragma unroll 8
        for (int j = 0; j < 32; ++j) {
            float4 pj = *(const float4*)&pw[j * 4];          // broadcast
            u64 vj = *(const u64*)&vs[(cbase + j) * 64 + 2 * lane];
            o2[0] = fma2(pk2(pj.x, pj.x), vj, o2[0]);
            o2[1] = fma2(pk2(pj.y, pj.y), vj, o2[1]);
            o2[2] = fma2(pk2(pj.z, pj.z), vj, o2[2]);
            o2[3] = fma2(pk2(pj.w, pj.w), vj, o2[3]);
        }
        __syncwarp();
    }

    // ---- merge the two cc-halves, write output
    __syncthreads();
    float* obuf = sm;          // [16][64]
    float* mbuf = sm + 1024;   // [16]
    float* lbuf = sm + 1040;   // [16]
    if (w >= 4) {
        #pragma unroll
        for (int rr = 0; rr < 4; ++rr) {
            int r = r0 + rr;
            float lo, hi; upk2(o2[rr], lo, hi);
            obuf[r * 64 + 2 * lane]     = lo;
            obuf[r * 64 + 2 * lane + 1] = hi;
            if (lane == 0) { mbuf[r] = m[rr]; lbuf[r] = l[rr]; }
        }
    }
    __syncthreads();
    if (w < 4) {
        #pragma unroll
        for (int rr = 0; rr < 4; ++rr) {
            int r = r0 + rr;
            float mo = mbuf[r], lo_o = lbuf[r];
            float mn = fmaxf(m[rr], mo);
            float ca = __expf(m[rr] - mn);
            float cb = __expf(mo - mn);
            float inv = 1.f / (l[rr] * ca + lo_o * cb);
            float alo, ahi; upk2(o2[rr], alo, ahi);
            float blo = obuf[r * 64 + 2 * lane];
            float bhi = obuf[r * 64 + 2 * lane + 1];
            float* op = outp + (size_t)(bt0 + r) * 512 + h * 64 + 2 * lane;
            op[0] = (alo * ca + blo * cb) * inv;
            op[1] = (ahi * ca + bhi * cb) * inv;
        }
    }
}

// ---------------------------------------------------------------------------
extern "C" void kernel_launch(void* const* d_in, const int* in_sizes, int n_in,
                              void* d_out, int out_size)
{
    const float* model_embed = (const float*)d_in[0];
    const float* ctx_key     = (const float*)d_in[1];
    const float* ctx_val     = (const float*)d_in[2];
    const float* ln1w = (const float*)d_in[3];
    const float* ln1b = (const float*)d_in[4];
    const float* ln2w = (const float*)d_in[5];
    const float* ln2b = (const float*)d_in[6];
    const float* ln3w = (const float*)d_in[7];
    const float* ln3b = (const float*)d_in[8];
    const float* ln4w = (const float*)d_in[9];
    const float* ln4b = (const float*)d_in[10];
    const float* wq = (const float*)d_in[11];
    const float* bq = (const float*)d_in[12];
    const float* wk = (const float*)d_in[13];
    const float* bk = (const float*)d_in[14];
    const float* wv = (const float*)d_in[15];
    const float* bv = (const float*)d_in[16];
    const float* wo = (const float*)d_in[17];
    const float* bo = (const float*)d_in[18];
    const float* wp = (const float*)d_in[19];
    const float* bp = (const float*)d_in[20];

    float *xn, *q, *k, *v, *att, *o;
    cudaGetSymbolAddress((void**)&xn,  g_xn);
    cudaGetSymbolAddress((void**)&q,   g_q);
    cudaGetSymbolAddress((void**)&k,   g_k);
    cudaGetSymbolAddress((void**)&v,   g_v);
    cudaGetSymbolAddress((void**)&att, g_att);
    cudaGetSymbolAddress((void**)&o,   g_o);

    static int smem_set = 0;
    if (!smem_set) {
        cudaFuncSetAttribute(attn_kernel,
                             cudaFuncAttributeMaxDynamicSharedMemorySize, ATT_SMEM);
        smem_set = 1;
    }

    ln_kernel<<<128,  256>>>(model_embed, ln1w, ln1b, xn);
    sgemm_small<<<dim3(32, 4), 128>>>(xn, wq, bq, q);
    ln_kernel<<<1024, 256>>>(ctx_key, ln2w, ln2b, xn);
    sgemm_big<<<dim3(64, 4), 256>>>(xn, wk, bk, k);
    ln_kernel<<<256,  256>>>(ctx_val, ln3w, ln3b, xn);
    sgemm_small<<<dim3(64, 4), 128>>>(xn, wv, bv, v);

    attn_kernel<<<dim3(64, 8), 256, ATT_SMEM>>>(q, k, v, att);

    sgemm_small<<<dim3(32, 4), 128>>>(att, wo, bo, o);
    ln_kernel<<<128, 256>>>(o, ln4w, ln4b, xn);
    sgemm_small<<<dim3(32, 4), 128>>>(xn, wp, bp, (float*)d_out);
}

// round 6
// speedup vs baseline: 3.0530x; 1.0318x over previous
#include <cuda_runtime.h>
#include <cstdint>
#include <math.h>

// Shapes fixed: B=4, T=256, C=2048, U=4, D=512, P=512, H=8, dk=64

__device__ float g_xnq[1024 * 512];
__device__ float g_xnk[8192 * 512];
__device__ float g_xnv[2048 * 512];
__device__ float g_q  [1024 * 512];
__device__ float g_k  [8192 * 512];
__device__ float g_v  [2048 * 512];
__device__ float g_att[1024 * 512];
__device__ float g_o  [1024 * 512];

typedef unsigned long long u64;

__device__ __forceinline__ u64 pk2(float lo, float hi) {
    u64 r; asm("mov.b64 %0, {%1, %2};" : "=l"(r) : "f"(lo), "f"(hi)); return r;
}
__device__ __forceinline__ void upk2(u64 v, float& lo, float& hi) {
    asm("mov.b64 {%0, %1}, %2;" : "=f"(lo), "=f"(hi) : "l"(v));
}
__device__ __forceinline__ u64 fma2(u64 a, u64 b, u64 c) {
    u64 d; asm("fma.rn.f32x2 %0, %1, %2, %3;" : "=l"(d) : "l"(a), "l"(b), "l"(c)); return d;
}
__device__ __forceinline__ u64 mul2(u64 a, u64 b) {
    u64 d; asm("mul.rn.f32x2 %0, %1, %2;" : "=l"(d) : "l"(a), "l"(b)); return d;
}

// ---------------------------------------------------------------------------
// LayerNorm row worker: one warp per row, D=512.
// ---------------------------------------------------------------------------
__device__ __forceinline__ void ln_row(
    const float* __restrict__ xr, const float* __restrict__ w,
    const float* __restrict__ b, float* __restrict__ orow, int lane)
{
    float4 xv[4];
    float s = 0.f, ss = 0.f;
    #pragma unroll
    for (int j = 0; j < 4; ++j) {
        xv[j] = *(const float4*)&xr[j * 128 + lane * 4];
        s  += xv[j].x + xv[j].y + xv[j].z + xv[j].w;
        ss += xv[j].x * xv[j].x + xv[j].y * xv[j].y + xv[j].z * xv[j].z + xv[j].w * xv[j].w;
    }
    #pragma unroll
    for (int o = 16; o; o >>= 1) {
        s  += __shfl_xor_sync(0xffffffffu, s, o);
        ss += __shfl_xor_sync(0xffffffffu, ss, o);
    }
    float mu = s * (1.f / 512.f);
    float rstd = rsqrtf(ss * (1.f / 512.f) - mu * mu + 1e-5f);
    #pragma unroll
    for (int j = 0; j < 4; ++j) {
        int col = j * 128 + lane * 4;
        float4 wv = *(const float4*)&w[col];
        float4 bv = *(const float4*)&b[col];
        float4 ov;
        ov.x = (xv[j].x - mu) * rstd * wv.x + bv.x;
        ov.y = (xv[j].y - mu) * rstd * wv.y + bv.y;
        ov.z = (xv[j].z - mu) * rstd * wv.z + bv.z;
        ov.w = (xv[j].w - mu) * rstd * wv.w + bv.w;
        *(float4*)&orow[col] = ov;
    }
}

// Single LN (for ln4). grid = rows/8, block 256.
__global__ __launch_bounds__(256) void ln_kernel(
    const float* __restrict__ x, const float* __restrict__ w,
    const float* __restrict__ b, float* __restrict__ out)
{
    const int lane = threadIdx.x & 31;
    const size_t row = (size_t)blockIdx.x * 8 + (threadIdx.x >> 5);
    ln_row(x + row * 512, w, b, out + row * 512, lane);
}

// Batched LN for q/k/v inputs. Blocks: [0,128) q, [128,1152) k, [1152,1408) v.
__global__ __launch_bounds__(256) void ln_batched(
    const float* __restrict__ x0, const float* __restrict__ w0, const float* __restrict__ b0, float* __restrict__ o0,
    const float* __restrict__ x1, const float* __restrict__ w1, const float* __restrict__ b1, float* __restrict__ o1,
    const float* __restrict__ x2, const float* __restrict__ w2, const float* __restrict__ b2, float* __restrict__ o2)
{
    const int lane = threadIdx.x & 31;
    const int bx = blockIdx.x;
    const float *x, *w, *b; float* o; size_t rb;
    if (bx < 128)       { x = x0; w = w0; b = b0; o = o0; rb = (size_t)bx * 8; }
    else if (bx < 1152) { x = x1; w = w1; b = b1; o = o1; rb = (size_t)(bx - 128) * 8; }
    else                { x = x2; w = w2; b = b2; o = o2; rb = (size_t)(bx - 1152) * 8; }
    const size_t row = rb + (threadIdx.x >> 5);
    ln_row(x + row * 512, w, b, o + row * 512, lane);
}

// ---------------------------------------------------------------------------
// sgemm_big inner: 128x128 tile, BK=16, 256 threads, 8x8 thread tile,
// pair-strided columns (conflict-free). Double-buffered.
// ---------------------------------------------------------------------------
__device__ __forceinline__ void sgemm_big_body(
    const float* __restrict__ A, const float* __restrict__ B,
    const float* __restrict__ bias, float* __restrict__ C,
    size_t m0, int n0)
{
    __shared__ float As[2][16][132];
    __shared__ float Bs[2][16][132];

    const int tid = threadIdx.x;
    const int ty = tid >> 4;
    const int tx = tid & 15;

    const int ar  = tid >> 1;
    const int ak4 = (tid & 1) * 8;
    const int bk  = tid >> 4;
    const int bn  = (tid & 15) * 8;

    u64 acc[8][4];
    #pragma unroll
    for (int i = 0; i < 8; ++i)
        #pragma unroll
        for (int j = 0; j < 4; ++j) acc[i][j] = 0ull;

    float4 la0 = *(const float4*)&A[(m0 + ar) * 512 + ak4];
    float4 la1 = *(const float4*)&A[(m0 + ar) * 512 + ak4 + 4];
    float4 lb0 = *(const float4*)&B[(size_t)bk * 512 + n0 + bn];
    float4 lb1 = *(const float4*)&B[(size_t)bk * 512 + n0 + bn + 4];
    {
        As[0][ak4 + 0][ar] = la0.x; As[0][ak4 + 1][ar] = la0.y;
        As[0][ak4 + 2][ar] = la0.z; As[0][ak4 + 3][ar] = la0.w;
        As[0][ak4 + 4][ar] = la1.x; As[0][ak4 + 5][ar] = la1.y;
        As[0][ak4 + 6][ar] = la1.z; As[0][ak4 + 7][ar] = la1.w;
        *(float4*)&Bs[0][bk][bn]     = lb0;
        *(float4*)&Bs[0][bk][bn + 4] = lb1;
    }
    __syncthreads();

    for (int kt = 0; kt < 32; ++kt) {
        const int buf = kt & 1;
        if (kt < 31) {
            const int k0 = (kt + 1) * 16;
            la0 = *(const float4*)&A[(m0 + ar) * 512 + k0 + ak4];
            la1 = *(const float4*)&A[(m0 + ar) * 512 + k0 + ak4 + 4];
            lb0 = *(const float4*)&B[(size_t)(k0 + bk) * 512 + n0 + bn];
            lb1 = *(const float4*)&B[(size_t)(k0 + bk) * 512 + n0 + bn + 4];
        }
        #pragma unroll
        for (int kk = 0; kk < 16; ++kk) {
            float4 a0 = *(const float4*)&As[buf][kk][ty * 8];
            float4 a1 = *(const float4*)&As[buf][kk][ty * 8 + 4];
            u64 b0 = *(const u64*)&Bs[buf][kk][2 * tx];
            u64 b1 = *(const u64*)&Bs[buf][kk][2 * tx + 32];
            u64 b2 = *(const u64*)&Bs[buf][kk][2 * tx + 64];
            u64 b3 = *(const u64*)&Bs[buf][kk][2 * tx + 96];
            float av[8] = {a0.x, a0.y, a0.z, a0.w, a1.x, a1.y, a1.z, a1.w};
            #pragma unroll
            for (int i = 0; i < 8; ++i) {
                u64 ai = pk2(av[i], av[i]);
                acc[i][0] = fma2(ai, b0, acc[i][0]);
                acc[i][1] = fma2(ai, b1, acc[i][1]);
                acc[i][2] = fma2(ai, b2, acc[i][2]);
                acc[i][3] = fma2(ai, b3, acc[i][3]);
            }
        }
        if (kt < 31) {
            const int nb = 1 - buf;
            As[nb][ak4 + 0][ar] = la0.x; As[nb][ak4 + 1][ar] = la0.y;
            As[nb][ak4 + 2][ar] = la0.z; As[nb][ak4 + 3][ar] = la0.w;
            As[nb][ak4 + 4][ar] = la1.x; As[nb][ak4 + 5][ar] = la1.y;
            As[nb][ak4 + 6][ar] = la1.z; As[nb][ak4 + 7][ar] = la1.w;
            *(float4*)&Bs[nb][bk][bn]     = lb0;
            *(float4*)&Bs[nb][bk][bn + 4] = lb1;
        }
        __syncthreads();
    }

    #pragma unroll
    for (int j = 0; j < 4; ++j) {
        const int col = n0 + 2 * tx + 32 * j;
        float2 bb = *(const float2*)&bias[col];
        #pragma unroll
        for (int i = 0; i < 8; ++i) {
            float o0, o1; upk2(acc[i][j], o0, o1);
            *(float2*)&C[(m0 + ty * 8 + i) * 512 + col] =
                make_float2(o0 + bb.x, o1 + bb.y);
        }
    }
}

// Batched q/k/v projection GEMM. grid (88, 4): bx [0,8) q, [8,72) k, [72,88) v.
__global__ __launch_bounds__(256) void sgemm_big3(
    const float* __restrict__ Aq, const float* __restrict__ Wq, const float* __restrict__ Bq, float* __restrict__ Cq,
    const float* __restrict__ Ak, const float* __restrict__ Wk, const float* __restrict__ Bk, float* __restrict__ Ck,
    const float* __restrict__ Av, const float* __restrict__ Wv, const float* __restrict__ Bv, float* __restrict__ Cv)
{
    const int bx = blockIdx.x;
    const int n0 = blockIdx.y * 128;
    if (bx < 8)
        sgemm_big_body(Aq, Wq, Bq, Cq, (size_t)bx * 128, n0);
    else if (bx < 72)
        sgemm_big_body(Ak, Wk, Bk, Ck, (size_t)(bx - 8) * 128, n0);
    else
        sgemm_big_body(Av, Wv, Bv, Cv, (size_t)(bx - 72) * 128, n0);
}

// ---------------------------------------------------------------------------
// sgemm_small: 32x128 tile, BK=16, 128 threads, 4x8 thread tile. grid (M/32,4).
// ---------------------------------------------------------------------------
__global__ __launch_bounds__(128) void sgemm_small(
    const float* __restrict__ A, const float* __restrict__ B,
    const float* __restrict__ bias, float* __restrict__ C)
{
    __shared__ float As[2][16][36];
    __shared__ float Bs[2][16][132];

    const int tid = threadIdx.x;
    const int ty = tid >> 4;
    const int tx = tid & 15;
    const size_t m0 = (size_t)blockIdx.x * 32;
    const int n0 = blockIdx.y * 128;

    const int ar  = tid >> 2;
    const int ak4 = (tid & 3) * 4;
    const int bk  = tid >> 4;
    const int bn  = (tid & 15) * 8;

    u64 acc[4][4];
    #pragma unroll
    for (int i = 0; i < 4; ++i)
        #pragma unroll
        for (int j = 0; j < 4; ++j) acc[i][j] = 0ull;

    float4 la = *(const float4*)&A[(m0 + ar) * 512 + ak4];
    float4 lb0 = *(const float4*)&B[(size_t)bk * 512 + n0 + bn];
    float4 lb1 = *(const float4*)&B[(size_t)bk * 512 + n0 + bn + 4];
    float4 lb2 = *(const float4*)&B[(size_t)(bk + 8) * 512 + n0 + bn];
    float4 lb3 = *(const float4*)&B[(size_t)(bk + 8) * 512 + n0 + bn + 4];
    {
        As[0][ak4 + 0][ar] = la.x; As[0][ak4 + 1][ar] = la.y;
        As[0][ak4 + 2][ar] = la.z; As[0][ak4 + 3][ar] = la.w;
        *(float4*)&Bs[0][bk][bn]         = lb0;
        *(float4*)&Bs[0][bk][bn + 4]     = lb1;
        *(float4*)&Bs[0][bk + 8][bn]     = lb2;
        *(float4*)&Bs[0][bk + 8][bn + 4] = lb3;
    }
    __syncthreads();

    for (int kt = 0; kt < 32; ++kt) {
        const int buf = kt & 1;
        if (kt < 31) {
            const int k0 = (kt + 1) * 16;
            la  = *(const float4*)&A[(m0 + ar) * 512 + k0 + ak4];
            lb0 = *(const float4*)&B[(size_t)(k0 + bk) * 512 + n0 + bn];
            lb1 = *(const float4*)&B[(size_t)(k0 + bk) * 512 + n0 + bn + 4];
            lb2 = *(const float4*)&B[(size_t)(k0 + bk + 8) * 512 + n0 + bn];
            lb3 = *(const float4*)&B[(size_t)(k0 + bk + 8) * 512 + n0 + bn + 4];
        }
        #pragma unroll
        for (int kk = 0; kk < 16; ++kk) {
            float4 a0 = *(const float4*)&As[buf][kk][ty * 4];
            u64 b0 = *(const u64*)&Bs[buf][kk][2 * tx];
            u64 b1 = *(const u64*)&Bs[buf][kk][2 * tx + 32];
            u64 b2 = *(const u64*)&Bs[buf][kk][2 * tx + 64];
            u64 b3 = *(const u64*)&Bs[buf][kk][2 * tx + 96];
            float av[4] = {a0.x, a0.y, a0.z, a0.w};
            #pragma unroll
            for (int i = 0; i < 4; ++i) {
                u64 ai = pk2(av[i], av[i]);
                acc[i][0] = fma2(ai, b0, acc[i][0]);
                acc[i][1] = fma2(ai, b1, acc[i][1]);
                acc[i][2] = fma2(ai, b2, acc[i][2]);
                acc[i][3] = fma2(ai, b3, acc[i][3]);
            }
        }
        if (kt < 31) {
            const int nb = 1 - buf;
            As[nb][ak4 + 0][ar] = la.x; As[nb][ak4 + 1][ar] = la.y;
            As[nb][ak4 + 2][ar] = la.z; As[nb][ak4 + 3][ar] = la.w;
            *(float4*)&Bs[nb][bk][bn]         = lb0;
            *(float4*)&Bs[nb][bk][bn + 4]     = lb1;
            *(float4*)&Bs[nb][bk + 8][bn]     = lb2;
            *(float4*)&Bs[nb][bk + 8][bn + 4] = lb3;
        }
        __syncthreads();
    }

    #pragma unroll
    for (int j = 0; j < 4; ++j) {
        const int col = n0 + 2 * tx + 32 * j;
        float2 bb = *(const float2*)&bias[col];
        #pragma unroll
        for (int i = 0; i < 4; ++i) {
            float o0, o1; upk2(acc[i][j], o0, o1);
            *(float2*)&C[(m0 + ty * 4 + i) * 512 + col] =
                make_float2(o0 + bb.x, o1 + bb.y);
        }
    }
}

// ---------------------------------------------------------------------------
// Fused ColBERT attention. Block 256 thr / 8 warps, grid (32, 8).
// 32-token tile; warp w owns rows 4w..4w+3; each warp sees all 32 ccs
// of each chunk (lane = cc). u64 (f32x2) loads straight from smem - no movs.
// smem: qs[32*64] | ks[4][32][64] swizzled | vs[32*64] | pd[8][32][8]
// ---------------------------------------------------------------------------
#define ATT_SMEM ((2048 + 8192 + 2048 + 2048) * 4)

__global__ __launch_bounds__(256) void attn_kernel(
    const float* __restrict__ q, const float* __restrict__ k,
    const float* __restrict__ v, float* __restrict__ outp)
{
    extern __shared__ float sm[];
    float* qs = sm;                  // [32][64]
    float* ks = sm + 2048;           // [u][cc][64] swizzled
    float* vs = ks + 8192;           // [cc][64]
    float* pd = vs + 2048;           // [warp][cc][8] duplicated p

    const int tid  = threadIdx.x;
    const int w    = tid >> 5;
    const int lane = tid & 31;
    const int h    = blockIdx.y;
    const int bt0  = blockIdx.x * 32;
    const int r0   = w * 4;
    const int sw   = (lane & 7) << 2;

    // Q tile: 512 float4s
    #pragma unroll
    for (int j = 0; j < 2; ++j) {
        int i = tid + 256 * j;
        int dd = i & 15, r = i >> 4;
        *(float4*)&qs[r * 64 + dd * 4] =
            *(const float4*)&q[(size_t)(bt0 + r) * 512 + h * 64 + dd * 4];
    }

    float m[4] = {-1e30f, -1e30f, -1e30f, -1e30f};
    float l[4] = {0.f, 0.f, 0.f, 0.f};
    u64 o2[4]  = {0ull, 0ull, 0ull, 0ull};

    const float* kb0 = ks + lane * 64;
    const float* kb1 = kb0 + 2048;
    const float* kb2 = kb0 + 4096;
    const float* kb3 = kb0 + 6144;
    float* pw = pd + w * 256;

    for (int c0 = 0; c0 < 2048; c0 += 32) {
        __syncthreads();
        // K chunk: 2048 float4s, swizzled STS.128
        #pragma unroll
        for (int j = 0; j < 8; ++j) {
            int i = tid + 256 * j;
            int dd = i & 15, u = (i >> 4) & 3, cc = i >> 6;
            float4 t = *(const float4*)&k[((size_t)(c0 + cc) * 4 + u) * 512 + h * 64 + dd * 4];
            *(float4*)&ks[u * 2048 + cc * 64 + ((dd << 2) ^ ((cc & 7) << 2))] = t;
        }
        // V chunk: 512 float4s
        #pragma unroll
        for (int j = 0; j < 2; ++j) {
            int i = tid + 256 * j;
            int dd = i & 15, cc = i >> 4;
            *(float4*)&vs[cc * 64 + dd * 4] =
                *(const float4*)&v[(size_t)(c0 + cc) * 512 + h * 64 + dd * 4];
        }
        __syncthreads();

        // ---- scores: acc[r][u], all operands loaded as packed u64 pairs
        u64 acc[4][4];
        #pragma unroll
        for (int r = 0; r < 4; ++r)
            #pragma unroll
            for (int u = 0; u < 4; ++u) acc[r][u] = 0ull;

        #pragma unroll
        for (int d4 = 0; d4 < 64; d4 += 4) {
            const int off = d4 ^ sw;
            ulonglong2 k0 = *(const ulonglong2*)&kb0[off];
            ulonglong2 k1 = *(const ulonglong2*)&kb1[off];
            ulonglong2 k2 = *(const ulonglong2*)&kb2[off];
            ulonglong2 k3 = *(const ulonglong2*)&kb3[off];
            ulonglong2 q0 = *(const ulonglong2*)&qs[(r0 + 0) * 64 + d4];
            ulonglong2 q1 = *(const ulonglong2*)&qs[(r0 + 1) * 64 + d4];
            ulonglong2 q2 = *(const ulonglong2*)&qs[(r0 + 2) * 64 + d4];
            ulonglong2 q3 = *(const ulonglong2*)&qs[(r0 + 3) * 64 + d4];
            acc[0][0] = fma2(q0.x, k0.x, acc[0][0]); acc[0][0] = fma2(q0.y, k0.y, acc[0][0]);
            acc[0][1] = fma2(q0.x, k1.x, acc[0][1]); acc[0][1] = fma2(q0.y, k1.y, acc[0][1]);
            acc[0][2] = fma2(q0.x, k2.x, acc[0][2]); acc[0][2] = fma2(q0.y, k2.y, acc[0][2]);
            acc[0][3] = fma2(q0.x, k3.x, acc[0][3]); acc[0][3] = fma2(q0.y, k3.y, acc[0][3]);
            acc[1][0] = fma2(q1.x, k0.x, acc[1][0]); acc[1][0] = fma2(q1.y, k0.y, acc[1][0]);
            acc[1][1] = fma2(q1.x, k1.x, acc[1][1]); acc[1][1] = fma2(q1.y, k1.y, acc[1][1]);
            acc[1][2] = fma2(q1.x, k2.x, acc[1][2]); acc[1][2] = fma2(q1.y, k2.y, acc[1][2]);
            acc[1][3] = fma2(q1.x, k3.x, acc[1][3]); acc[1][3] = fma2(q1.y, k3.y, acc[1][3]);
            acc[2][0] = fma2(q2.x, k0.x, acc[2][0]); acc[2][0] = fma2(q2.y, k0.y, acc[2][0]);
            acc[2][1] = fma2(q2.x, k1.x, acc[2][1]); acc[2][1] = fma2(q2.y, k1.y, acc[2][1]);
            acc[2][2] = fma2(q2.x, k2.x, acc[2][2]); acc[2][2] = fma2(q2.y, k2.y, acc[2][2]);
            acc[2][3] = fma2(q2.x, k3.x, acc[2][3]); acc[2][3] = fma2(q2.y, k3.y, acc[2][3]);
            acc[3][0] = fma2(q3.x, k0.x, acc[3][0]); acc[3][0] = fma2(q3.y, k0.y, acc[3][0]);
            acc[3][1] = fma2(q3.x, k1.x, acc[3][1]); acc[3][1] = fma2(q3.y, k1.y, acc[3][1]);
            acc[3][2] = fma2(q3.x, k2.x, acc[3][2]); acc[3][2] = fma2(q3.y, k2.y, acc[3][2]);
            acc[3][3] = fma2(q3.x, k3.x, acc[3][3]); acc[3][3] = fma2(q3.y, k3.y, acc[3][3]);
        }

        float pv[4];
        #pragma unroll
        for (int r = 0; r < 4; ++r) {
            float x0, x1, s;
            upk2(acc[r][0], x0, x1); s = x0 + x1;
            upk2(acc[r][1], x0, x1); s = fmaxf(s, x0 + x1);
            upk2(acc[r][2], x0, x1); s = fmaxf(s, x0 + x1);
            upk2(acc[r][3], x0, x1); s = fmaxf(s, x0 + x1);
            s *= 0.125f;
            float cm = s;
            #pragma unroll
            for (int o = 16; o; o >>= 1)
                cm = fmaxf(cm, __shfl_xor_sync(0xffffffffu, cm, o));
            float mn   = fmaxf(m[r], cm);
            float corr = __expf(m[r] - mn);
            pv[r] = __expf(s - mn);
            float pssum = pv[r];
            #pragma unroll
            for (int o = 16; o; o >>= 1)
                pssum += __shfl_xor_sync(0xffffffffu, pssum, o);
            l[r] = l[r] * corr + pssum;
            m[r] = mn;
            o2[r] = mul2(o2[r], pk2(corr, corr));
        }

        // store duplicated p: pd[w][cc][2r],[2r+1] = p[r]
        *(float4*)&pw[lane * 8]     = make_float4(pv[0], pv[0], pv[1], pv[1]);
        *(float4*)&pw[lane * 8 + 4] = make_float4(pv[2], pv[2], pv[3], pv[3]);
        __syncwarp();

        // ---- AV: o[r][2lane..] += p[r][j] * v[j][2lane..]
        #pragma unroll 8
        for (int j = 0; j < 32; ++j) {
            u64 vj = *(const u64*)&vs[j * 64 + 2 * lane];
            const u64* pj = (const u64*)&pw[j * 8];
            o2[0] = fma2(pj[0], vj, o2[0]);
            o2[1] = fma2(pj[1], vj, o2[1]);
            o2[2] = fma2(pj[2], vj, o2[2]);
            o2[3] = fma2(pj[3], vj, o2[3]);
        }
        __syncwarp();
    }

    // ---- normalize + write (no cross-warp merge needed)
    #pragma unroll
    for (int r = 0; r < 4; ++r) {
        float inv = 1.f / l[r];
        float lo, hi; upk2(o2[r], lo, hi);
        *(float2*)&outp[(size_t)(bt0 + r0 + r) * 512 + h * 64 + 2 * lane] =
            make_float2(lo * inv, hi * inv);
    }
}

// ---------------------------------------------------------------------------
extern "C" void kernel_launch(void* const* d_in, const int* in_sizes, int n_in,
                              void* d_out, int out_size)
{
    const float* model_embed = (const float*)d_in[0];
    const float* ctx_key     = (const float*)d_in[1];
    const float* ctx_val     = (const float*)d_in[2];
    const float* ln1w = (const float*)d_in[3];
    const float* ln1b = (const float*)d_in[4];
    const float* ln2w = (const float*)d_in[5];
    const float* ln2b = (const float*)d_in[6];
    const float* ln3w = (const float*)d_in[7];
    const float* ln3b = (const float*)d_in[8];
    const float* ln4w = (const float*)d_in[9];
    const float* ln4b = (const float*)d_in[10];
    const float* wq = (const float*)d_in[11];
    const float* bq = (const float*)d_in[12];
    const float* wk = (const float*)d_in[13];
    const float* bk = (const float*)d_in[14];
    const float* wv = (const float*)d_in[15];
    const float* bv = (const float*)d_in[16];
    const float* wo = (const float*)d_in[17];
    const float* bo = (const float*)d_in[18];
    const float* wp = (const float*)d_in[19];
    const float* bp = (const float*)d_in[20];

    float *xnq, *xnk, *xnv, *q, *k, *v, *att, *o;
    cudaGetSymbolAddress((void**)&xnq, g_xnq);
    cudaGetSymbolAddress((void**)&xnk, g_xnk);
    cudaGetSymbolAddress((void**)&xnv, g_xnv);
    cudaGetSymbolAddress((void**)&q,   g_q);
    cudaGetSymbolAddress((void**)&k,   g_k);
    cudaGetSymbolAddress((void**)&v,   g_v);
    cudaGetSymbolAddress((void**)&att, g_att);
    cudaGetSymbolAddress((void**)&o,   g_o);

    static int attr_set = 0;
    if (!attr_set) {
        cudaFuncSetAttribute(attn_kernel,
                             cudaFuncAttributeMaxDynamicSharedMemorySize, ATT_SMEM);
        attr_set = 1;
    }

    // batched LN for q/k/v inputs
    ln_batched<<<1408, 256>>>(model_embed, ln1w, ln1b, xnq,
                              ctx_key,     ln2w, ln2b, xnk,
                              ctx_val,     ln3w, ln3b, xnv);
    // batched q/k/v projections
    sgemm_big3<<<dim3(88, 4), 256>>>(xnq, wq, bq, q,
                                     xnk, wk, bk, k,
                                     xnv, wv, bv, v);
    // fused MaxSim attention
    attn_kernel<<<dim3(32, 8), 256, ATT_SMEM>>>(q, k, v, att);

    // output proj, LN4, final proj
    sgemm_small<<<dim3(32, 4), 128>>>(att, wo, bo, o);
    ln_kernel<<<128, 256>>>(o, ln4w, ln4b, xnq);
    sgemm_small<<<dim3(32, 4), 128>>>(xnq, wp, bp, (float*)d_out);
}

// round 7
// speedup vs baseline: 3.8667x; 1.2665x over previous
#include <cuda_runtime.h>
#include <cstdint>
#include <math.h>

// Shapes fixed: B=4, T=256, C=2048, U=4, D=512, P=512, H=8, dk=64

__device__ float2 g_stats[11264];   // mu/rstd for q(1024)|k(8192)|v(2048) rows
__device__ float2 g_stats4[1024];   // mu/rstd for LN4
__device__ float g_q  [1024 * 512];
__device__ float g_k  [8192 * 512];
__device__ float g_v  [2048 * 512];
__device__ float g_att[1024 * 512];
__device__ float g_o  [1024 * 512];

typedef unsigned long long u64;

__device__ __forceinline__ u64 pk2(float lo, float hi) {
    u64 r; asm("mov.b64 %0, {%1, %2};" : "=l"(r) : "f"(lo), "f"(hi)); return r;
}
__device__ __forceinline__ void upk2(u64 v, float& lo, float& hi) {
    asm("mov.b64 {%0, %1}, %2;" : "=f"(lo), "=f"(hi) : "l"(v));
}
__device__ __forceinline__ u64 fma2(u64 a, u64 b, u64 c) {
    u64 d; asm("fma.rn.f32x2 %0, %1, %2, %3;" : "=l"(d) : "l"(a), "l"(b), "l"(c)); return d;
}
__device__ __forceinline__ u64 mul2(u64 a, u64 b) {
    u64 d; asm("mul.rn.f32x2 %0, %1, %2;" : "=l"(d) : "l"(a), "l"(b)); return d;
}
__device__ __forceinline__ uint32_t smem_u32(const void* p) {
    uint32_t a;
    asm("{ .reg .u64 t; cvta.to.shared.u64 t, %1; cvt.u32.u64 %0, t; }" : "=r"(a) : "l"(p));
    return a;
}
#define CP_ASYNC16(dst, src) \
    asm volatile("cp.async.cg.shared.global [%0], [%1], 16;" :: "r"(dst), "l"(src) : "memory")
#define CP_COMMIT() asm volatile("cp.async.commit_group;" ::: "memory")
#define CP_WAIT(n)  asm volatile("cp.async.wait_group %0;" :: "n"(n) : "memory")

// ---------------------------------------------------------------------------
// LN stats: one warp per row, D=512. Writes (mu, rstd).
// ---------------------------------------------------------------------------
__device__ __forceinline__ void ln_stat_row(
    const float* __restrict__ xr, float2* __restrict__ out, int lane)
{
    float s = 0.f, ss = 0.f;
    #pragma unroll
    for (int j = 0; j < 4; ++j) {
        float4 x = *(const float4*)&xr[j * 128 + lane * 4];
        s  += x.x + x.y + x.z + x.w;
        ss += x.x * x.x + x.y * x.y + x.z * x.z + x.w * x.w;
    }
    #pragma unroll
    for (int o = 16; o; o >>= 1) {
        s  += __shfl_xor_sync(0xffffffffu, s, o);
        ss += __shfl_xor_sync(0xffffffffu, ss, o);
    }
    if (lane == 0) {
        float mu = s * (1.f / 512.f);
        float rstd = rsqrtf(ss * (1.f / 512.f) - mu * mu + 1e-5f);
        *out = make_float2(mu, rstd);
    }
}

// Batched stats for the three projection inputs.
__global__ __launch_bounds__(256) void ln_stats3(
    const float* __restrict__ x0, const float* __restrict__ x1,
    const float* __restrict__ x2, float2* __restrict__ st)
{
    const int lane = threadIdx.x & 31;
    const int wr = threadIdx.x >> 5;
    const int bx = blockIdx.x;
    const float* x; size_t row; float2* o;
    if (bx < 128)       { x = x0; row = (size_t)bx * 8 + wr; o = st; }
    else if (bx < 1152) { x = x1; row = (size_t)(bx - 128) * 8 + wr; o = st + 1024; }
    else                { x = x2; row = (size_t)(bx - 1152) * 8 + wr; o = st + 9216; }
    ln_stat_row(x + row * 512, o + row, lane);
}

__global__ __launch_bounds__(256) void ln_stats1(
    const float* __restrict__ x, float2* __restrict__ st)
{
    const int lane = threadIdx.x & 31;
    const size_t row = (size_t)blockIdx.x * 8 + (threadIdx.x >> 5);
    ln_stat_row(x + row * 512, st + row, lane);
}

// ---------------------------------------------------------------------------
// sgemm_big with fused LN on A-load: 128x128 tile, BK=16, 256 thr, 8x8 tile.
// ---------------------------------------------------------------------------
__device__ __forceinline__ void sgemm_big_body_ln(
    const float* __restrict__ A, const float2* __restrict__ stats,
    const float* __restrict__ lnw, const float* __restrict__ lnb,
    const float* __restrict__ B, const float* __restrict__ bias,
    float* __restrict__ C, size_t m0, int n0)
{
    __shared__ float As[2][16][132];
    __shared__ float Bs[2][16][132];

    const int tid = threadIdx.x;
    const int ty = tid >> 4, tx = tid & 15;
    const int ar = tid >> 1, ak4 = (tid & 1) * 8;
    const int bk = tid >> 4, bn = (tid & 15) * 8;

    const float2 st = stats[m0 + ar];

    u64 acc[8][4];
    #pragma unroll
    for (int i = 0; i < 8; ++i)
        #pragma unroll
        for (int j = 0; j < 4; ++j) acc[i][j] = 0ull;

    float4 la0, la1, lb0, lb1;
    // transformed A load
    {
        float4 r0 = *(const float4*)&A[(m0 + ar) * 512 + ak4];
        float4 r1 = *(const float4*)&A[(m0 + ar) * 512 + ak4 + 4];
        float4 w0 = *(const float4*)&lnw[ak4];
        float4 w1 = *(const float4*)&lnw[ak4 + 4];
        float4 b0 = *(const float4*)&lnb[ak4];
        float4 b1 = *(const float4*)&lnb[ak4 + 4];
        la0.x = (r0.x - st.x) * st.y * w0.x + b0.x;
        la0.y = (r0.y - st.x) * st.y * w0.y + b0.y;
        la0.z = (r0.z - st.x) * st.y * w0.z + b0.z;
        la0.w = (r0.w - st.x) * st.y * w0.w + b0.w;
        la1.x = (r1.x - st.x) * st.y * w1.x + b1.x;
        la1.y = (r1.y - st.x) * st.y * w1.y + b1.y;
        la1.z = (r1.z - st.x) * st.y * w1.z + b1.z;
        la1.w = (r1.w - st.x) * st.y * w1.w + b1.w;
    }
    lb0 = *(const float4*)&B[(size_t)bk * 512 + n0 + bn];
    lb1 = *(const float4*)&B[(size_t)bk * 512 + n0 + bn + 4];
    {
        As[0][ak4 + 0][ar] = la0.x; As[0][ak4 + 1][ar] = la0.y;
        As[0][ak4 + 2][ar] = la0.z; As[0][ak4 + 3][ar] = la0.w;
        As[0][ak4 + 4][ar] = la1.x; As[0][ak4 + 5][ar] = la1.y;
        As[0][ak4 + 6][ar] = la1.z; As[0][ak4 + 7][ar] = la1.w;
        *(float4*)&Bs[0][bk][bn]     = lb0;
        *(float4*)&Bs[0][bk][bn + 4] = lb1;
    }
    __syncthreads();

    for (int kt = 0; kt < 32; ++kt) {
        const int buf = kt & 1;
        if (kt < 31) {
            const int k0 = (kt + 1) * 16;
            float4 r0 = *(const float4*)&A[(m0 + ar) * 512 + k0 + ak4];
            float4 r1 = *(const float4*)&A[(m0 + ar) * 512 + k0 + ak4 + 4];
            float4 w0 = *(const float4*)&lnw[k0 + ak4];
            float4 w1 = *(const float4*)&lnw[k0 + ak4 + 4];
            float4 b0 = *(const float4*)&lnb[k0 + ak4];
            float4 b1 = *(const float4*)&lnb[k0 + ak4 + 4];
            la0.x = (r0.x - st.x) * st.y * w0.x + b0.x;
            la0.y = (r0.y - st.x) * st.y * w0.y + b0.y;
            la0.z = (r0.z - st.x) * st.y * w0.z + b0.z;
            la0.w = (r0.w - st.x) * st.y * w0.w + b0.w;
            la1.x = (r1.x - st.x) * st.y * w1.x + b1.x;
            la1.y = (r1.y - st.x) * st.y * w1.y + b1.y;
            la1.z = (r1.z - st.x) * st.y * w1.z + b1.z;
            la1.w = (r1.w - st.x) * st.y * w1.w + b1.w;
            lb0 = *(const float4*)&B[(size_t)(k0 + bk) * 512 + n0 + bn];
            lb1 = *(const float4*)&B[(size_t)(k0 + bk) * 512 + n0 + bn + 4];
        }
        #pragma unroll
        for (int kk = 0; kk < 16; ++kk) {
            float4 a0 = *(const float4*)&As[buf][kk][ty * 8];
            float4 a1 = *(const float4*)&As[buf][kk][ty * 8 + 4];
            u64 b0 = *(const u64*)&Bs[buf][kk][2 * tx];
            u64 b1 = *(const u64*)&Bs[buf][kk][2 * tx + 32];
            u64 b2 = *(const u64*)&Bs[buf][kk][2 * tx + 64];
            u64 b3 = *(const u64*)&Bs[buf][kk][2 * tx + 96];
            float av[8] = {a0.x, a0.y, a0.z, a0.w, a1.x, a1.y, a1.z, a1.w};
            #pragma unroll
            for (int i = 0; i < 8; ++i) {
                u64 ai = pk2(av[i], av[i]);
                acc[i][0] = fma2(ai, b0, acc[i][0]);
                acc[i][1] = fma2(ai, b1, acc[i][1]);
                acc[i][2] = fma2(ai, b2, acc[i][2]);
                acc[i][3] = fma2(ai, b3, acc[i][3]);
            }
        }
        if (kt < 31) {
            const int nb = 1 - buf;
            As[nb][ak4 + 0][ar] = la0.x; As[nb][ak4 + 1][ar] = la0.y;
            As[nb][ak4 + 2][ar] = la0.z; As[nb][ak4 + 3][ar] = la0.w;
            As[nb][ak4 + 4][ar] = la1.x; As[nb][ak4 + 5][ar] = la1.y;
            As[nb][ak4 + 6][ar] = la1.z; As[nb][ak4 + 7][ar] = la1.w;
            *(float4*)&Bs[nb][bk][bn]     = lb0;
            *(float4*)&Bs[nb][bk][bn + 4] = lb1;
        }
        __syncthreads();
    }

    #pragma unroll
    for (int j = 0; j < 4; ++j) {
        const int col = n0 + 2 * tx + 32 * j;
        float2 bb = *(const float2*)&bias[col];
        #pragma unroll
        for (int i = 0; i < 8; ++i) {
            float o0, o1; upk2(acc[i][j], o0, o1);
            *(float2*)&C[(m0 + ty * 8 + i) * 512 + col] =
                make_float2(o0 + bb.x, o1 + bb.y);
        }
    }
}

// Batched q/k/v projections with fused LN. grid (88, 4).
__global__ __launch_bounds__(256) void sgemm_big3(
    const float* __restrict__ Aq, const float2* __restrict__ Sq, const float* __restrict__ W1q, const float* __restrict__ B1q, const float* __restrict__ Wq, const float* __restrict__ Bq, float* __restrict__ Cq,
    const float* __restrict__ Ak, const float2* __restrict__ Sk, const float* __restrict__ W1k, const float* __restrict__ B1k, const float* __restrict__ Wk, const float* __restrict__ Bk, float* __restrict__ Ck,
    const float* __restrict__ Av, const float2* __restrict__ Sv, const float* __restrict__ W1v, const float* __restrict__ B1v, const float* __restrict__ Wv, const float* __restrict__ Bv, float* __restrict__ Cv)
{
    const int bx = blockIdx.x;
    const int n0 = blockIdx.y * 128;
    if (bx < 8)
        sgemm_big_body_ln(Aq, Sq, W1q, B1q, Wq, Bq, Cq, (size_t)bx * 128, n0);
    else if (bx < 72)
        sgemm_big_body_ln(Ak, Sk, W1k, B1k, Wk, Bk, Ck, (size_t)(bx - 8) * 128, n0);
    else
        sgemm_big_body_ln(Av, Sv, W1v, B1v, Wv, Bv, Cv, (size_t)(bx - 72) * 128, n0);
}

// ---------------------------------------------------------------------------
// Tail GEMM: 32x128 tile, BK=16, 256 threads, 2x8 thread tile, optional
// fused LN on A-load. grid (M/32, 4).
// ---------------------------------------------------------------------------
__global__ __launch_bounds__(256) void sgemm_tail(
    const float* __restrict__ A, const float* __restrict__ B,
    const float* __restrict__ bias, float* __restrict__ C,
    const float2* __restrict__ stats, const float* __restrict__ lnw,
    const float* __restrict__ lnb, int do_ln)
{
    __shared__ float As[2][16][36];
    __shared__ float Bs[2][16][132];

    const int tid = threadIdx.x;
    const int ty = tid >> 4;            // 0..15, rows ty*2
    const int tx = tid & 15;
    const size_t m0 = (size_t)blockIdx.x * 32;
    const int n0 = blockIdx.y * 128;

    const int ar  = tid >> 2;           // 0..63 (only tid<128 loads A)
    const int ak4 = (tid & 3) * 4;
    const int bk  = tid >> 4;
    const int bn  = (tid & 15) * 8;
    const bool aload = tid < 128;

    float2 st = make_float2(0.f, 1.f);
    if (do_ln && aload) st = stats[m0 + ar];

    u64 acc[2][4];
    #pragma unroll
    for (int i = 0; i < 2; ++i)
        #pragma unroll
        for (int j = 0; j < 4; ++j) acc[i][j] = 0ull;

    float4 la = make_float4(0, 0, 0, 0);
    float4 lb0, lb1, lb2, lb3;
    if (aload) {
        float4 r = *(const float4*)&A[(m0 + ar) * 512 + ak4];
        if (do_ln) {
            float4 w = *(const float4*)&lnw[ak4];
            float4 b = *(const float4*)&lnb[ak4];
            la.x = (r.x - st.x) * st.y * w.x + b.x;
            la.y = (r.y - st.x) * st.y * w.y + b.y;
            la.z = (r.z - st.x) * st.y * w.z + b.z;
            la.w = (r.w - st.x) * st.y * w.w + b.w;
        } else la = r;
    }
    lb0 = *(const float4*)&B[(size_t)bk * 512 + n0 + bn];
    lb1 = *(const float4*)&B[(size_t)bk * 512 + n0 + bn + 4];
    lb2 = lb0; lb3 = lb1; // placeholders (bk covers 16 rows directly)
    if (aload) {
        As[0][ak4 + 0][ar] = la.x; As[0][ak4 + 1][ar] = la.y;
        As[0][ak4 + 2][ar] = la.z; As[0][ak4 + 3][ar] = la.w;
    }
    *(float4*)&Bs[0][bk][bn]     = lb0;
    *(float4*)&Bs[0][bk][bn + 4] = lb1;
    __syncthreads();

    for (int kt = 0; kt < 32; ++kt) {
        const int buf = kt & 1;
        if (kt < 31) {
            const int k0 = (kt + 1) * 16;
            if (aload) {
                float4 r = *(const float4*)&A[(m0 + ar) * 512 + k0 + ak4];
                if (do_ln) {
                    float4 w = *(const float4*)&lnw[k0 + ak4];
                    float4 b = *(const float4*)&lnb[k0 + ak4];
                    la.x = (r.x - st.x) * st.y * w.x + b.x;
                    la.y = (r.y - st.x) * st.y * w.y + b.y;
                    la.z = (r.z - st.x) * st.y * w.z + b.z;
                    la.w = (r.w - st.x) * st.y * w.w + b.w;
                } else la = r;
            }
            lb0 = *(const float4*)&B[(size_t)(k0 + bk) * 512 + n0 + bn];
            lb1 = *(const float4*)&B[(size_t)(k0 + bk) * 512 + n0 + bn + 4];
        }
        #pragma unroll
        for (int kk = 0; kk < 16; ++kk) {
            float2 a = *(const float2*)&As[buf][kk][ty * 2];
            u64 b0 = *(const u64*)&Bs[buf][kk][2 * tx];
            u64 b1 = *(const u64*)&Bs[buf][kk][2 * tx + 32];
            u64 b2 = *(const u64*)&Bs[buf][kk][2 * tx + 64];
            u64 b3 = *(const u64*)&Bs[buf][kk][2 * tx + 96];
            u64 a0 = pk2(a.x, a.x), a1 = pk2(a.y, a.y);
            acc[0][0] = fma2(a0, b0, acc[0][0]);
            acc[0][1] = fma2(a0, b1, acc[0][1]);
            acc[0][2] = fma2(a0, b2, acc[0][2]);
            acc[0][3] = fma2(a0, b3, acc[0][3]);
            acc[1][0] = fma2(a1, b0, acc[1][0]);
            acc[1][1] = fma2(a1, b1, acc[1][1]);
            acc[1][2] = fma2(a1, b2, acc[1][2]);
            acc[1][3] = fma2(a1, b3, acc[1][3]);
        }
        if (kt < 31) {
            const int nb = 1 - buf;
            if (aload) {
                As[nb][ak4 + 0][ar] = la.x; As[nb][ak4 + 1][ar] = la.y;
                As[nb][ak4 + 2][ar] = la.z; As[nb][ak4 + 3][ar] = la.w;
            }
            *(float4*)&Bs[nb][bk][bn]     = lb0;
            *(float4*)&Bs[nb][bk][bn + 4] = lb1;
        }
        __syncthreads();
    }

    #pragma unroll
    for (int j = 0; j < 4; ++j) {
        const int col = n0 + 2 * tx + 32 * j;
        float2 bb = *(const float2*)&bias[col];
        #pragma unroll
        for (int i = 0; i < 2; ++i) {
            float o0, o1; upk2(acc[i][j], o0, o1);
            *(float2*)&C[(m0 + ty * 2 + i) * 512 + col] =
                make_float2(o0 + bb.x, o1 + bb.y);
        }
    }
}

// ---------------------------------------------------------------------------
// Fused ColBERT attention. Block 256 thr / 8 warps, grid (16, 8).
// 64-token tile, 8 rows per warp, lane = cc (chunk 32), cp.async
// double-buffered K/V staging, swizzled K smem, smem p-transpose AV.
// smem floats: qs[4096] | ks[2*8192] | vs[2*2048] | pd[2048]  = 104 KB
// ---------------------------------------------------------------------------
#define ATT_SMEM (26624 * 4)

__global__ __launch_bounds__(256, 1) void attn_kernel(
    const float* __restrict__ q, const float* __restrict__ k,
    const float* __restrict__ v, float* __restrict__ outp)
{
    extern __shared__ float sm[];
    float* qs  = sm;             // [64][64]
    float* ksb = sm + 4096;      // 2 x [u][cc][64] swizzled
    float* vsb = sm + 20480;     // 2 x [cc][64]
    float* pd  = sm + 24576;     // [warp][cc][8]

    const int tid  = threadIdx.x;
    const int w    = tid >> 5;
    const int lane = tid & 31;
    const int h    = blockIdx.y;
    const int bt0  = blockIdx.x * 64;
    const int r0   = w * 8;
    const int sw   = (lane & 7) << 2;
    const uint32_t smb = smem_u32(sm);

    // ---- staging address precompute (affine in j)
    const int scc = tid >> 3, srr = tid & 7;              // K: cc, dd-group
    const float* kg = k + ((size_t)scc * 4) * 512 + h * 64 + srr * 4;
    const uint32_t koff0 = (uint32_t)(scc * 64 + ((srr * 4) ^ ((scc & 7) << 2)));
    const float* vg = v + (size_t)(tid >> 4) * 512 + h * 64 + (tid & 15) * 4;
    const uint32_t voff0 = (uint32_t)((tid >> 4) * 64 + (tid & 15) * 4);

    // ---- Q staging (plain): 1024 float4
    #pragma unroll
    for (int j = 0; j < 4; ++j) {
        int i = tid + 256 * j;
        int dd = i & 15, r = i >> 4;
        *(float4*)&qs[r * 64 + dd * 4] =
            *(const float4*)&q[(size_t)(bt0 + r) * 512 + h * 64 + dd * 4];
    }

    // ---- stage chunk c into buffer b (cp.async)
    auto stage = [&](int b, int c) {
        const float* kp = kg + (size_t)c * 65536;
        const uint32_t kd = smb + (4096 + b * 8192 + koff0) * 4;
        #pragma unroll
        for (int j = 0; j < 8; ++j)
            CP_ASYNC16(kd + (uint32_t)(((j & 1) * 32 + (j >> 1) * 2048) * 4),
                       kp + (j >> 1) * 512 + (j & 1) * 32);
        const float* vp = vg + (size_t)c * 16384;
        const uint32_t vd = smb + (20480 + b * 2048 + voff0) * 4;
        CP_ASYNC16(vd, vp);
        CP_ASYNC16(vd + 1024 * 4, vp + 8192);
    };

    stage(0, 0); CP_COMMIT();

    float m[8], l[8];
    u64 o2[8];
    #pragma unroll
    for (int r = 0; r < 8; ++r) { m[r] = -1e30f; l[r] = 0.f; o2[r] = 0ull; }

    float* pw = pd + w * 256;

    for (int c = 0; c < 64; ++c) {
        const int buf = c & 1;
        if (c < 63) { stage(buf ^ 1, c + 1); CP_COMMIT(); CP_WAIT(1); }
        else        { CP_WAIT(0); }
        __syncthreads();

        const float* ks = ksb + buf * 8192;
        const float* vs = vsb + buf * 2048;
        const float* kb = ks + lane * 64;

        // ---- scores: acc[r][u], 8 rows x 4 u per warp
        u64 acc[8][4];
        #pragma unroll
        for (int r = 0; r < 8; ++r)
            #pragma unroll
            for (int u = 0; u < 4; ++u) acc[r][u] = 0ull;

        #pragma unroll
        for (int d4 = 0; d4 < 64; d4 += 4) {
            const int off = d4 ^ sw;
            ulonglong2 k0 = *(const ulonglong2*)&kb[off];
            ulonglong2 k1 = *(const ulonglong2*)&kb[off + 2048];
            ulonglong2 k2 = *(const ulonglong2*)&kb[off + 4096];
            ulonglong2 k3 = *(const ulonglong2*)&kb[off + 6144];
            #pragma unroll
            for (int r = 0; r < 8; ++r) {
                ulonglong2 qq = *(const ulonglong2*)&qs[(r0 + r) * 64 + d4];
                acc[r][0] = fma2(qq.x, k0.x, acc[r][0]);
                acc[r][0] = fma2(qq.y, k0.y, acc[r][0]);
                acc[r][1] = fma2(qq.x, k1.x, acc[r][1]);
                acc[r][1] = fma2(qq.y, k1.y, acc[r][1]);
                acc[r][2] = fma2(qq.x, k2.x, acc[r][2]);
                acc[r][2] = fma2(qq.y, k2.y, acc[r][2]);
                acc[r][3] = fma2(qq.x, k3.x, acc[r][3]);
                acc[r][3] = fma2(qq.y, k3.y, acc[r][3]);
            }
        }

        // ---- MaxSim + online softmax
        float pv[8];
        #pragma unroll
        for (int r = 0; r < 8; ++r) {
            float x0, x1, s;
            upk2(acc[r][0], x0, x1); s = x0 + x1;
            upk2(acc[r][1], x0, x1); s = fmaxf(s, x0 + x1);
            upk2(acc[r][2], x0, x1); s = fmaxf(s, x0 + x1);
            upk2(acc[r][3], x0, x1); s = fmaxf(s, x0 + x1);
            s *= 0.125f;
            float cm = s;
            #pragma unroll
            for (int o = 16; o; o >>= 1)
                cm = fmaxf(cm, __shfl_xor_sync(0xffffffffu, cm, o));
            float mn   = fmaxf(m[r], cm);
            float corr = __expf(m[r] - mn);
            pv[r] = __expf(s - mn);
            float ps = pv[r];
            #pragma unroll
            for (int o = 16; o; o >>= 1)
                ps += __shfl_xor_sync(0xffffffffu, ps, o);
            l[r] = l[r] * corr + ps;
            m[r] = mn;
            o2[r] = mul2(o2[r], pk2(corr, corr));
        }

        // transpose p through smem: pd[w][cc][r]
        *(float4*)&pw[lane * 8]     = make_float4(pv[0], pv[1], pv[2], pv[3]);
        *(float4*)&pw[lane * 8 + 4] = make_float4(pv[4], pv[5], pv[6], pv[7]);
        __syncwarp();

        // ---- AV: o[r][2lane..] += p[r][j] * v[j][2lane..]
        #pragma unroll 4
        for (int j = 0; j < 32; ++j) {
            u64 vj = *(const u64*)&vs[j * 64 + 2 * lane];
            float4 pa = *(const float4*)&pw[j * 8];
            float4 pb = *(const float4*)&pw[j * 8 + 4];
            o2[0] = fma2(pk2(pa.x, pa.x), vj, o2[0]);
            o2[1] = fma2(pk2(pa.y, pa.y), vj, o2[1]);
            o2[2] = fma2(pk2(pa.z, pa.z), vj, o2[2]);
            o2[3] = fma2(pk2(pa.w, pa.w), vj, o2[3]);
            o2[4] = fma2(pk2(pb.x, pb.x), vj, o2[4]);
            o2[5] = fma2(pk2(pb.y, pb.y), vj, o2[5]);
            o2[6] = fma2(pk2(pb.z, pb.z), vj, o2[6]);
            o2[7] = fma2(pk2(pb.w, pb.w), vj, o2[7]);
        }
        __syncwarp();
        __syncthreads();
    }

    // ---- normalize + write
    #pragma unroll
    for (int r = 0; r < 8; ++r) {
        float inv = 1.f / l[r];
        float lo, hi; upk2(o2[r], lo, hi);
        *(float2*)&outp[(size_t)(bt0 + r0 + r) * 512 + h * 64 + 2 * lane] =
            make_float2(lo * inv, hi * inv);
    }
}

// ---------------------------------------------------------------------------
extern "C" void kernel_launch(void* const* d_in, const int* in_sizes, int n_in,
                              void* d_out, int out_size)
{
    const float* model_embed = (const float*)d_in[0];
    const float* ctx_key     = (const float*)d_in[1];
    const float* ctx_val     = (const float*)d_in[2];
    const float* ln1w = (const float*)d_in[3];
    const float* ln1b = (const float*)d_in[4];
    const float* ln2w = (const float*)d_in[5];
    const float* ln2b = (const float*)d_in[6];
    const float* ln3w = (const float*)d_in[7];
    const float* ln3b = (const float*)d_in[8];
    const float* ln4w = (const float*)d_in[9];
    const float* ln4b = (const float*)d_in[10];
    const float* wq = (const float*)d_in[11];
    const float* bq = (const float*)d_in[12];
    const float* wk = (const float*)d_in[13];
    const float* bk = (const float*)d_in[14];
    const float* wv = (const float*)d_in[15];
    const float* bv = (const float*)d_in[16];
    const float* wo = (const float*)d_in[17];
    const float* bo = (const float*)d_in[18];
    const float* wp = (const float*)d_in[19];
    const float* bp = (const float*)d_in[20];

    float2 *stats, *stats4;
    float *q, *k, *v, *att, *o;
    cudaGetSymbolAddress((void**)&stats,  g_stats);
    cudaGetSymbolAddress((void**)&stats4, g_stats4);
    cudaGetSymbolAddress((void**)&q,   g_q);
    cudaGetSymbolAddress((void**)&k,   g_k);
    cudaGetSymbolAddress((void**)&v,   g_v);
    cudaGetSymbolAddress((void**)&att, g_att);
    cudaGetSymbolAddress((void**)&o,   g_o);

    static int attr_set = 0;
    if (!attr_set) {
        cudaFuncSetAttribute(attn_kernel,
                             cudaFuncAttributeMaxDynamicSharedMemorySize, ATT_SMEM);
        attr_set = 1;
    }

    // LN stats for q/k/v inputs, then fused LN+GEMM projections
    ln_stats3<<<1408, 256>>>(model_embed, ctx_key, ctx_val, stats);
    sgemm_big3<<<dim3(88, 4), 256>>>(
        model_embed, stats,        ln1w, ln1b, wq, bq, q,
        ctx_key,     stats + 1024, ln2w, ln2b, wk, bk, k,
        ctx_val,     stats + 9216, ln3w, ln3b, wv, bv, v);

    // fused MaxSim attention
    attn_kernel<<<dim3(16, 8), 256, ATT_SMEM>>>(q, k, v, att);

    // output proj, LN4-fused final proj
    sgemm_tail<<<dim3(32, 4), 256>>>(att, wo, bo, o, nullptr, nullptr, nullptr, 0);
    ln_stats1<<<128, 256>>>(o, stats4);
    sgemm_tail<<<dim3(32, 4), 256>>>(o, wp, bp, (float*)d_out, stats4, ln4w, ln4b, 1);
}